// round 9
// baseline (speedup 1.0000x reference)
#include <cuda_runtime.h>
#include <cuda_fp16.h>
#include <math.h>
#include <cstdint>

#define HID 256
#define NHEAD 8
#define DK 32
#define MAXN 50048
#define MAXE 1048576

// ---------------- device scratch (allocation-free rule) ----------------
__device__ __half g_qh[MAXN * HID];     // q (fp16)
__device__ __half g_kh[MAXN * HID];     // k (fp16)
__device__ __half g_vh[MAXN * HID];     // v (fp16)
__device__ __half g_ah[MAXN * HID];     // ctx hi -> later wv hi
__device__ __half g_al[MAXN * HID];     // wv lo
__device__ __half g_nh[MAXN * HID];     // node hi
__device__ __half g_wt[4 * HID * HID];  // Wt fp16 [n][k], 4 slots
// CSR
__device__ int g_cnt[MAXN];
__device__ int g_off[MAXN];
__device__ int g_cur[MAXN];
__device__ int g_esrc[MAXE];
__device__ int g_bsum[256];

// ---------------- helpers ----------------
__device__ __forceinline__ uint32_t smem_u32(const void* p) {
    uint32_t a;
    asm("{ .reg .u64 t; cvta.to.shared.u64 t, %1; cvt.u32.u64 %0, t; }"
        : "=r"(a) : "l"(p));
    return a;
}
__device__ __forceinline__ void ldsm4(uint32_t (&r)[4], uint32_t addr) {
    asm volatile("ldmatrix.sync.aligned.m8n8.x4.shared.b16 {%0,%1,%2,%3}, [%4];"
                 : "=r"(r[0]), "=r"(r[1]), "=r"(r[2]), "=r"(r[3]) : "r"(addr));
}
__device__ __forceinline__ void mma16816h(float (&c)[4], const uint32_t (&a)[4],
                                          uint32_t b0, uint32_t b1) {
    asm volatile(
        "mma.sync.aligned.m16n8k16.row.col.f32.f16.f16.f32 "
        "{%0,%1,%2,%3}, {%4,%5,%6,%7}, {%8,%9}, {%0,%1,%2,%3};"
        : "+f"(c[0]), "+f"(c[1]), "+f"(c[2]), "+f"(c[3])
        : "r"(a[0]), "r"(a[1]), "r"(a[2]), "r"(a[3]), "r"(b0), "r"(b1));
}
__device__ __forceinline__ void cpasync16(uint32_t s, const void* g) {
    asm volatile("cp.async.cg.shared.global [%0], [%1], 16;"
                 :: "r"(s), "l"(g) : "memory");
}
__device__ __forceinline__ void cp_commit() {
    asm volatile("cp.async.commit_group;" ::: "memory");
}
template <int N>
__device__ __forceinline__ void cp_wait() {
    asm volatile("cp.async.wait_group %0;" :: "n"(N) : "memory");
}

// ---------------- conversion kernels ----------------
__global__ void conv_w_all(const float* __restrict__ W0, const float* __restrict__ W1,
                           const float* __restrict__ W2, const float* __restrict__ W3) {
    int idx = blockIdx.x * blockDim.x + threadIdx.x;  // 4*65536
    int slot = idx >> 16;
    int r = idx & 65535;
    int k = r >> 8, n = r & 255;
    const float* W = (slot == 0) ? W0 : (slot == 1) ? W1 : (slot == 2) ? W2 : W3;
    g_wt[slot * HID * HID + n * HID + k] = __float2half_rn(W[k * HID + n]);
}

// fp32 -> fp16 hi only
__global__ void conv_hi(const float* __restrict__ in, __half* __restrict__ hi, int n4) {
    int i = blockIdx.x * blockDim.x + threadIdx.x;
    if (i >= n4) return;
    float4 v = ((const float4*)in)[i];
    ((__half2*)hi)[2 * i] = __floats2half2_rn(v.x, v.y);
    ((__half2*)hi)[2 * i + 1] = __floats2half2_rn(v.z, v.w);
}

// ------- HMMA fp16 GEMM, cp.async double-buffered ------------------------
// C[M,256] = (Ah [+ Al]) @ Wt^T (+bias). All operands fp16 in global.
// CTA 128x128, 8 warps (4m x 2n), warp tile 32x64, K chunks of 64, 2 stages.
#define PADH 72
#define BUFB (128 * PADH * 2)  // 18432 bytes per buffer

template <int NPROD, bool OUT_HALF>
__global__ void __launch_bounds__(256, 2) gemm_db(
    const __half* __restrict__ Ah, const __half* __restrict__ Al,
    const __half* __restrict__ Bt, const float* __restrict__ bias,
    void* __restrict__ Cout, int M) {
    extern __shared__ char smraw[];
    const uint32_t smb = smem_u32(smraw);
    constexpr int S = NPROD + 1;  // buffers per stage

    const int tid = threadIdx.x, wid = tid >> 5, lane = tid & 31;
    const int bm = blockIdx.x * 128, bn = blockIdx.y * 128;
    const int wm = wid & 3, wn = wid >> 2;

    const uint32_t aRow = lane & 15, aColOff = (lane >> 4) * 8;
    const uint32_t bg = lane >> 3;
    const uint32_t bRowOff = (bg >> 1) * 8 + (lane & 7), bColOff = (bg & 1) * 8;

    float acc[2][8][4];
#pragma unroll
    for (int mb = 0; mb < 2; ++mb)
#pragma unroll
        for (int nb = 0; nb < 8; ++nb)
#pragma unroll
            for (int t = 0; t < 4; ++t) acc[mb][nb][t] = 0.f;

    auto stage = [&](int c, int s) {
        const int k0 = c * 64;
        const uint32_t sb = smb + s * S * BUFB;
#pragma unroll
        for (int it = 0; it < 4; ++it) {
            int u = tid + it * 256;  // 1024 = 128 rows * 8 vec8
            int row = u >> 3, col8 = u & 7;
            uint32_t so = (uint32_t)(row * PADH + col8 * 8) * 2;
            int gr = bm + row;
            if (gr < M) {
                size_t ga = (size_t)gr * HID + k0 + col8 * 8;
                cpasync16(sb + so, Ah + ga);
                if (NPROD == 2) cpasync16(sb + BUFB + so, Al + ga);
            }
            cpasync16(sb + NPROD * BUFB + so,
                      Bt + (size_t)(bn + row) * HID + k0 + col8 * 8);
        }
    };

    stage(0, 0);
    cp_commit();
#pragma unroll
    for (int c = 0; c < 4; ++c) {
        if (c < 3) {
            stage(c + 1, (c + 1) & 1);
            cp_commit();
        }
        if (c < 3) cp_wait<1>(); else cp_wait<0>();
        __syncthreads();

        const uint32_t st = smb + (c & 1) * S * BUFB;
#pragma unroll
        for (int kk = 0; kk < 4; ++kk) {
            const uint32_t kb = kk * 16;
            uint32_t ah[2][4], al[2][4];
#pragma unroll
            for (int mb = 0; mb < 2; ++mb) {
                uint32_t aoff = st + ((wm * 32 + mb * 16 + aRow) * PADH + kb + aColOff) * 2;
                ldsm4(ah[mb], aoff);
                if (NPROD == 2) ldsm4(al[mb], aoff + BUFB);
            }
#pragma unroll
            for (int half = 0; half < 2; ++half) {
                uint32_t bh[2][4];
#pragma unroll
                for (int p = 0; p < 2; ++p) {
                    uint32_t boff = st + NPROD * BUFB +
                                    ((wn * 64 + half * 32 + p * 16 + bRowOff) * PADH +
                                     kb + bColOff) * 2;
                    ldsm4(bh[p], boff);
                }
#pragma unroll
                for (int p = 0; p < 2; ++p)
#pragma unroll
                    for (int q = 0; q < 2; ++q) {
                        int nb = half * 4 + p * 2 + q;
#pragma unroll
                        for (int mb = 0; mb < 2; ++mb) {
                            mma16816h(acc[mb][nb], ah[mb], bh[p][q * 2], bh[p][q * 2 + 1]);
                            if (NPROD == 2)
                                mma16816h(acc[mb][nb], al[mb], bh[p][q * 2], bh[p][q * 2 + 1]);
                        }
                    }
            }
        }
        __syncthreads();
    }

    const int rbase = bm + wm * 32 + (lane >> 2);
    const int cbase = bn + wn * 64 + (lane & 3) * 2;
#pragma unroll
    for (int mb = 0; mb < 2; ++mb) {
        int r0 = rbase + mb * 16;
#pragma unroll
        for (int nb = 0; nb < 8; ++nb) {
            int col = cbase + nb * 8;
            float bx = 0.f, by = 0.f;
            if (bias) { bx = bias[col]; by = bias[col + 1]; }
            float c0 = acc[mb][nb][0] + bx, c1 = acc[mb][nb][1] + by;
            float c2 = acc[mb][nb][2] + bx, c3 = acc[mb][nb][3] + by;
            if (OUT_HALF) {
                __half* C = (__half*)Cout;
                if (r0 < M) *(__half2*)(C + (size_t)r0 * HID + col) = __floats2half2_rn(c0, c1);
                if (r0 + 8 < M) *(__half2*)(C + (size_t)(r0 + 8) * HID + col) = __floats2half2_rn(c2, c3);
            } else {
                float* C = (float*)Cout;
                if (r0 < M) *(float2*)(C + (size_t)r0 * HID + col) = make_float2(c0, c1);
                if (r0 + 8 < M) *(float2*)(C + (size_t)(r0 + 8) * HID + col) = make_float2(c2, c3);
            }
        }
    }
}

// ---------------- CSR build ----------------
__global__ void zero_cnt(int n) {
    int i = blockIdx.x * blockDim.x + threadIdx.x;
    if (i < n) g_cnt[i] = 0;
}
__global__ void hist_kernel(const int* __restrict__ dst, int E) {
    int e = blockIdx.x * blockDim.x + threadIdx.x;
    if (e < E) atomicAdd(&g_cnt[dst[e]], 1);
}
__global__ void scanA(int n) {
    __shared__ int sd[256];
    int i = blockIdx.x * 256 + threadIdx.x;
    sd[threadIdx.x] = (i < n) ? g_cnt[i] : 0;
    __syncthreads();
#pragma unroll
    for (int d = 128; d > 0; d >>= 1) {
        if (threadIdx.x < d) sd[threadIdx.x] += sd[threadIdx.x + d];
        __syncthreads();
    }
    if (threadIdx.x == 0) g_bsum[blockIdx.x] = sd[0];
}
__global__ void scanB(int nb) {
    __shared__ int sd[256];
    int tid = threadIdx.x;
    int v = (tid < nb) ? g_bsum[tid] : 0;
    sd[tid] = v;
    __syncthreads();
#pragma unroll
    for (int d = 1; d < 256; d <<= 1) {
        int t = (tid >= d) ? sd[tid - d] : 0;
        __syncthreads();
        sd[tid] += t;
        __syncthreads();
    }
    if (tid < nb) g_bsum[tid] = sd[tid] - v;  // exclusive
}
__global__ void scanC(int n) {
    __shared__ int sd[256];
    int tid = threadIdx.x;
    int i = blockIdx.x * 256 + tid;
    int v = (i < n) ? g_cnt[i] : 0;
    sd[tid] = v;
    __syncthreads();
#pragma unroll
    for (int d = 1; d < 256; d <<= 1) {
        int t = (tid >= d) ? sd[tid - d] : 0;
        __syncthreads();
        sd[tid] += t;
        __syncthreads();
    }
    if (i < n) {
        int off = g_bsum[blockIdx.x] + sd[tid] - v;
        g_off[i] = off;
        g_cur[i] = off;
    }
}
__global__ void scatter_kernel(const int* __restrict__ src,
                               const int* __restrict__ dst, int E) {
    int e = blockIdx.x * blockDim.x + threadIdx.x;
    if (e < E) {
        int p = atomicAdd(&g_cur[dst[e]], 1);
        g_esrc[p] = src[e];
    }
}

// ---------------- aggregation: one warp per dst node ----------------
__device__ __forceinline__ float edge_score(const uint4& kk, const float4& q0,
                                            const float4& q1) {
    const __half2* kh = (const __half2*)&kk;
    float2 a = __half22float2(kh[0]), b = __half22float2(kh[1]);
    float2 c = __half22float2(kh[2]), d = __half22float2(kh[3]);
    float p = q0.x * a.x + q0.y * a.y + q0.z * b.x + q0.w * b.y +
              q1.x * c.x + q1.y * c.y + q1.z * d.x + q1.w * d.y;
    p += __shfl_xor_sync(0xffffffffu, p, 1);
    p += __shfl_xor_sync(0xffffffffu, p, 2);
    p *= 0.17677669529663687f;  // 1/sqrt(32)
    p = fminf(5.0f, fmaxf(-5.0f, p));
    return exp2f(p * 1.4426950408889634f);
}
__device__ __forceinline__ void accum_v(float (&acc)[8], float sc, const uint4& vv) {
    const __half2* vh = (const __half2*)&vv;
#pragma unroll
    for (int t = 0; t < 4; ++t) {
        float2 f = __half22float2(vh[t]);
        acc[2 * t] += sc * f.x;
        acc[2 * t + 1] += sc * f.y;
    }
}

__global__ void __launch_bounds__(256) aggregate_kernel(int base, int n) {
    int w = (int)((blockIdx.x * (size_t)blockDim.x + threadIdx.x) >> 5);
    int lane = threadIdx.x & 31;
    if (w >= n) return;
    w += base;
    int beg = g_off[w], deg = g_cnt[w];

    uint4 qq = *(const uint4*)(g_qh + (size_t)w * HID + lane * 8);
    const __half2* qh = (const __half2*)&qq;
    float2 qa = __half22float2(qh[0]), qb = __half22float2(qh[1]);
    float2 qc = __half22float2(qh[2]), qd = __half22float2(qh[3]);
    float4 q0 = make_float4(qa.x, qa.y, qb.x, qb.y);
    float4 q1 = make_float4(qc.x, qc.y, qd.x, qd.y);

    float acc[8] = {0, 0, 0, 0, 0, 0, 0, 0};
    float zacc = 0.f;

    int j = 0;
    for (; j + 4 <= deg; j += 4) {
        int s0 = g_esrc[beg + j + 0];
        int s1 = g_esrc[beg + j + 1];
        int s2 = g_esrc[beg + j + 2];
        int s3 = g_esrc[beg + j + 3];
        uint4 k0 = *(const uint4*)(g_kh + (size_t)s0 * HID + lane * 8);
        uint4 k1 = *(const uint4*)(g_kh + (size_t)s1 * HID + lane * 8);
        uint4 k2 = *(const uint4*)(g_kh + (size_t)s2 * HID + lane * 8);
        uint4 k3 = *(const uint4*)(g_kh + (size_t)s3 * HID + lane * 8);
        uint4 v0 = *(const uint4*)(g_vh + (size_t)s0 * HID + lane * 8);
        uint4 v1 = *(const uint4*)(g_vh + (size_t)s1 * HID + lane * 8);
        uint4 v2 = *(const uint4*)(g_vh + (size_t)s2 * HID + lane * 8);
        uint4 v3 = *(const uint4*)(g_vh + (size_t)s3 * HID + lane * 8);
        float sc0 = edge_score(k0, q0, q1);
        float sc1 = edge_score(k1, q0, q1);
        float sc2 = edge_score(k2, q0, q1);
        float sc3 = edge_score(k3, q0, q1);
        accum_v(acc, sc0, v0);
        accum_v(acc, sc1, v1);
        accum_v(acc, sc2, v2);
        accum_v(acc, sc3, v3);
        zacc += (sc0 + sc1) + (sc2 + sc3);
    }
    for (; j < deg; ++j) {
        int s0 = g_esrc[beg + j];
        uint4 k0 = *(const uint4*)(g_kh + (size_t)s0 * HID + lane * 8);
        uint4 v0 = *(const uint4*)(g_vh + (size_t)s0 * HID + lane * 8);
        float sc0 = edge_score(k0, q0, q1);
        accum_v(acc, sc0, v0);
        zacc += sc0;
    }

    // write normalized wv as fp16 hi/lo
    float inv = 1.0f / zacc;
    uint4 UH, UL;
    uint32_t* uh = (uint32_t*)&UH;
    uint32_t* ul = (uint32_t*)&UL;
#pragma unroll
    for (int t = 0; t < 4; ++t) {
        float a = acc[2 * t] * inv, b = acc[2 * t + 1] * inv;
        __half2 h = __floats2half2_rn(a, b);
        float2 hf = __half22float2(h);
        __half2 l = __floats2half2_rn(a - hf.x, b - hf.y);
        uh[t] = *(uint32_t*)&h;
        ul[t] = *(uint32_t*)&l;
    }
    *(uint4*)(g_ah + (size_t)w * HID + lane * 8) = UH;
    *(uint4*)(g_al + (size_t)w * HID + lane * 8) = UL;
}

// ---------------- launch ----------------
#define NCHUNK 4

extern "C" void kernel_launch(void* const* d_in, const int* in_sizes, int n_in,
                              void* d_out, int out_size) {
    const float* context = (const float*)d_in[0];
    const float* node    = (const float*)d_in[1];
    const float* Wq      = (const float*)d_in[2];
    const float* bq      = (const float*)d_in[3];
    const float* Wk      = (const float*)d_in[4];
    const float* Wv      = (const float*)d_in[5];
    const float* Wo      = (const float*)d_in[6];
    const float* bo      = (const float*)d_in[7];
    const int*   src     = (const int*)d_in[8];
    const int*   dst     = (const int*)d_in[9];
    float* out = (float*)d_out;

    int Nq = in_sizes[0] / HID;
    int Ns = in_sizes[1] / HID;
    int E  = in_sizes[8];

    __half *qb, *kb, *vb, *ah, *al, *nh, *wt;
    cudaGetSymbolAddress((void**)&qb, g_qh);
    cudaGetSymbolAddress((void**)&kb, g_kh);
    cudaGetSymbolAddress((void**)&vb, g_vh);
    cudaGetSymbolAddress((void**)&ah, g_ah);
    cudaGetSymbolAddress((void**)&al, g_al);
    cudaGetSymbolAddress((void**)&nh, g_nh);
    cudaGetSymbolAddress((void**)&wt, g_wt);

    static bool inited = false;
    static cudaStream_t sG, sC;
    static cudaEvent_t evF, evW, evG, evC, evO, evA[NCHUNK];
    if (!inited) {
        cudaFuncSetAttribute(gemm_db<1, true>, cudaFuncAttributeMaxDynamicSharedMemorySize, 2 * 2 * BUFB);
        cudaFuncSetAttribute(gemm_db<2, false>, cudaFuncAttributeMaxDynamicSharedMemorySize, 2 * 3 * BUFB);
        cudaStreamCreateWithFlags(&sG, cudaStreamNonBlocking);
        cudaStreamCreateWithFlags(&sC, cudaStreamNonBlocking);
        cudaEventCreateWithFlags(&evF, cudaEventDisableTiming);
        cudaEventCreateWithFlags(&evW, cudaEventDisableTiming);
        cudaEventCreateWithFlags(&evG, cudaEventDisableTiming);
        cudaEventCreateWithFlags(&evC, cudaEventDisableTiming);
        cudaEventCreateWithFlags(&evO, cudaEventDisableTiming);
        for (int i = 0; i < NCHUNK; ++i)
            cudaEventCreateWithFlags(&evA[i], cudaEventDisableTiming);
        inited = true;
    }

    dim3 gq((Ns + 127) / 128, 2), gkv((Nq + 127) / 128, 2);
    int nb = (Ns + 255) / 256;
    int n4s = Ns * HID / 4, n4q = Nq * HID / 4;

    // fork
    cudaEventRecord(evF, 0);
    cudaStreamWaitEvent(sG, evF, 0);
    cudaStreamWaitEvent(sC, evF, 0);

    // ---- stream sG: weights + ctx hi conv + k,v GEMMs (all NPROD=1) ----
    conv_w_all<<<1024, 256, 0, sG>>>(Wq, Wk, Wv, Wo);
    cudaEventRecord(evW, sG);
    conv_hi<<<(n4q + 255) / 256, 256, 0, sG>>>(context, ah, n4q);
    gemm_db<1, true><<<gkv, 256, 2 * 2 * BUFB, sG>>>(ah, nullptr, wt + 1 * HID * HID, nullptr, kb, Nq);
    gemm_db<1, true><<<gkv, 256, 2 * 2 * BUFB, sG>>>(ah, nullptr, wt + 2 * HID * HID, nullptr, vb, Nq);
    cudaEventRecord(evG, sG);

    // ---- stream sC: CSR + node conv + q GEMM ----
    zero_cnt<<<nb, 256, 0, sC>>>(Ns);
    hist_kernel<<<(E + 255) / 256, 256, 0, sC>>>(dst, E);
    scanA<<<nb, 256, 0, sC>>>(Ns);
    scanB<<<1, 256, 0, sC>>>(nb);
    scanC<<<nb, 256, 0, sC>>>(Ns);
    scatter_kernel<<<(E + 255) / 256, 256, 0, sC>>>(src, dst, E);
    conv_hi<<<(n4s + 255) / 256, 256, 0, sC>>>(node, nh, n4s);
    cudaStreamWaitEvent(sC, evW, 0);
    gemm_db<1, true><<<gq, 256, 2 * 2 * BUFB, sC>>>(nh, nullptr, wt + 0 * HID * HID, bq, qb, Ns);
    cudaEventRecord(evC, sC);

    // ---- join onto default stream ----
    cudaStreamWaitEvent(0, evG, 0);
    cudaStreamWaitEvent(0, evC, 0);

    // ---- aggregation (default stream) pipelined with out-GEMM (sG) ----
    int rows_per = ((Ns / NCHUNK + 127) / 128) * 128;
    int base = 0;
    for (int i = 0; i < NCHUNK && base < Ns; ++i) {
        int n = Ns - base < rows_per ? Ns - base : rows_per;
        aggregate_kernel<<<(n + 7) / 8, 256>>>(base, n);
        cudaEventRecord(evA[i], 0);
        cudaStreamWaitEvent(sG, evA[i], 0);
        dim3 gg((n + 127) / 128, 2);
        gemm_db<2, false><<<gg, 256, 2 * 3 * BUFB, sG>>>(
            ah + (size_t)base * HID, al + (size_t)base * HID, wt + 3 * HID * HID,
            bo, out + (size_t)base * HID, n);
        base += n;
    }
    cudaEventRecord(evO, sG);
    cudaStreamWaitEvent(0, evO, 0);
}

// round 10
// speedup vs baseline: 1.0822x; 1.0822x over previous
#include <cuda_runtime.h>
#include <cuda_fp16.h>
#include <math.h>
#include <cstdint>

#define HID 256
#define NHEAD 8
#define DK 32
#define MAXN 50048
#define MAXE 1048576

// ---------------- device scratch (allocation-free rule) ----------------
__device__ __half g_qh[MAXN * HID];     // q (fp16)
__device__ __half g_kh[MAXN * HID];     // k (fp16)
__device__ __half g_vh[MAXN * HID];     // v (fp16)
__device__ __half g_ah[MAXN * HID];     // ctx hi -> later wv hi
__device__ __half g_al[MAXN * HID];     // wv lo
__device__ __half g_nh[MAXN * HID];     // node hi
__device__ __half g_wt[4 * HID * HID];  // Wt fp16 [n][k], 4 slots (q,k,v,o)
// CSR
__device__ int g_cnt[MAXN];
__device__ int g_off[MAXN];
__device__ int g_cur[MAXN];
__device__ int g_esrc[MAXE];
__device__ int g_bsum[256];

// ---------------- helpers ----------------
__device__ __forceinline__ uint32_t smem_u32(const void* p) {
    uint32_t a;
    asm("{ .reg .u64 t; cvta.to.shared.u64 t, %1; cvt.u32.u64 %0, t; }"
        : "=r"(a) : "l"(p));
    return a;
}
__device__ __forceinline__ void ldsm4(uint32_t (&r)[4], uint32_t addr) {
    asm volatile("ldmatrix.sync.aligned.m8n8.x4.shared.b16 {%0,%1,%2,%3}, [%4];"
                 : "=r"(r[0]), "=r"(r[1]), "=r"(r[2]), "=r"(r[3]) : "r"(addr));
}
__device__ __forceinline__ void mma16816h(float (&c)[4], const uint32_t (&a)[4],
                                          uint32_t b0, uint32_t b1) {
    asm volatile(
        "mma.sync.aligned.m16n8k16.row.col.f32.f16.f16.f32 "
        "{%0,%1,%2,%3}, {%4,%5,%6,%7}, {%8,%9}, {%0,%1,%2,%3};"
        : "+f"(c[0]), "+f"(c[1]), "+f"(c[2]), "+f"(c[3])
        : "r"(a[0]), "r"(a[1]), "r"(a[2]), "r"(a[3]), "r"(b0), "r"(b1));
}
__device__ __forceinline__ void cpasync16(uint32_t s, const void* g) {
    asm volatile("cp.async.cg.shared.global [%0], [%1], 16;"
                 :: "r"(s), "l"(g) : "memory");
}
__device__ __forceinline__ void cp_commit() {
    asm volatile("cp.async.commit_group;" ::: "memory");
}
template <int N>
__device__ __forceinline__ void cp_wait() {
    asm volatile("cp.async.wait_group %0;" :: "n"(N) : "memory");
}

// ---------------- conversion kernels ----------------
__global__ void conv_w_all(const float* __restrict__ W0, const float* __restrict__ W1,
                           const float* __restrict__ W2, const float* __restrict__ W3) {
    int idx = blockIdx.x * blockDim.x + threadIdx.x;  // 4*65536
    int slot = idx >> 16;
    int r = idx & 65535;
    int k = r >> 8, n = r & 255;
    const float* W = (slot == 0) ? W0 : (slot == 1) ? W1 : (slot == 2) ? W2 : W3;
    g_wt[slot * HID * HID + n * HID + k] = __float2half_rn(W[k * HID + n]);
}

// fp32 -> fp16 hi only
__global__ void conv_hi(const float* __restrict__ in, __half* __restrict__ hi, int n4) {
    int i = blockIdx.x * blockDim.x + threadIdx.x;
    if (i >= n4) return;
    float4 v = ((const float4*)in)[i];
    ((__half2*)hi)[2 * i] = __floats2half2_rn(v.x, v.y);
    ((__half2*)hi)[2 * i + 1] = __floats2half2_rn(v.z, v.w);
}

// ------- HMMA fp16 GEMM, cp.async double-buffered ------------------------
// C[M,N] = (Ah [+ Al]) @ Wt^T (+bias). All operands fp16 in global.
// CTA 128x128, 8 warps (4m x 2n), warp tile 32x64, K chunks of 64, 2 stages.
// DUAL: B spans 512 n-rows (two weight slots); cols [0,256)->Cout, [256,512)->Cout2.
#define PADH 72
#define BUFB (128 * PADH * 2)  // 18432 bytes per buffer

template <int NPROD, bool OUT_HALF, bool DUAL>
__global__ void __launch_bounds__(256, 2) gemm_db(
    const __half* __restrict__ Ah, const __half* __restrict__ Al,
    const __half* __restrict__ Bt, const float* __restrict__ bias,
    void* __restrict__ Cout, void* __restrict__ Cout2, int M) {
    extern __shared__ char smraw[];
    const uint32_t smb = smem_u32(smraw);
    constexpr int S = NPROD + 1;  // buffers per stage

    const int tid = threadIdx.x, wid = tid >> 5, lane = tid & 31;
    const int bm = blockIdx.x * 128, bn = blockIdx.y * 128;
    const int wm = wid & 3, wn = wid >> 2;

    // output routing (DUAL: second half of n goes to Cout2)
    void* Csel = (DUAL && bn >= 256) ? Cout2 : Cout;
    const int bnl = DUAL ? (bn & 255) : bn;

    const uint32_t aRow = lane & 15, aColOff = (lane >> 4) * 8;
    const uint32_t bg = lane >> 3;
    const uint32_t bRowOff = (bg >> 1) * 8 + (lane & 7), bColOff = (bg & 1) * 8;

    float acc[2][8][4];
#pragma unroll
    for (int mb = 0; mb < 2; ++mb)
#pragma unroll
        for (int nb = 0; nb < 8; ++nb)
#pragma unroll
            for (int t = 0; t < 4; ++t) acc[mb][nb][t] = 0.f;

    auto stage = [&](int c, int s) {
        const int k0 = c * 64;
        const uint32_t sb = smb + s * S * BUFB;
#pragma unroll
        for (int it = 0; it < 4; ++it) {
            int u = tid + it * 256;  // 1024 = 128 rows * 8 vec8
            int row = u >> 3, col8 = u & 7;
            uint32_t so = (uint32_t)(row * PADH + col8 * 8) * 2;
            int gr = bm + row;
            if (gr < M) {
                size_t ga = (size_t)gr * HID + k0 + col8 * 8;
                cpasync16(sb + so, Ah + ga);
                if (NPROD == 2) cpasync16(sb + BUFB + so, Al + ga);
            }
            cpasync16(sb + NPROD * BUFB + so,
                      Bt + (size_t)(bn + row) * HID + k0 + col8 * 8);
        }
    };

    stage(0, 0);
    cp_commit();
#pragma unroll
    for (int c = 0; c < 4; ++c) {
        if (c < 3) {
            stage(c + 1, (c + 1) & 1);
            cp_commit();
        }
        if (c < 3) cp_wait<1>(); else cp_wait<0>();
        __syncthreads();

        const uint32_t st = smb + (c & 1) * S * BUFB;
#pragma unroll
        for (int kk = 0; kk < 4; ++kk) {
            const uint32_t kb = kk * 16;
            uint32_t ah[2][4], al[2][4];
#pragma unroll
            for (int mb = 0; mb < 2; ++mb) {
                uint32_t aoff = st + ((wm * 32 + mb * 16 + aRow) * PADH + kb + aColOff) * 2;
                ldsm4(ah[mb], aoff);
                if (NPROD == 2) ldsm4(al[mb], aoff + BUFB);
            }
#pragma unroll
            for (int half = 0; half < 2; ++half) {
                uint32_t bh[2][4];
#pragma unroll
                for (int p = 0; p < 2; ++p) {
                    uint32_t boff = st + NPROD * BUFB +
                                    ((wn * 64 + half * 32 + p * 16 + bRowOff) * PADH +
                                     kb + bColOff) * 2;
                    ldsm4(bh[p], boff);
                }
#pragma unroll
                for (int p = 0; p < 2; ++p)
#pragma unroll
                    for (int q = 0; q < 2; ++q) {
                        int nb = half * 4 + p * 2 + q;
#pragma unroll
                        for (int mb = 0; mb < 2; ++mb) {
                            mma16816h(acc[mb][nb], ah[mb], bh[p][q * 2], bh[p][q * 2 + 1]);
                            if (NPROD == 2)
                                mma16816h(acc[mb][nb], al[mb], bh[p][q * 2], bh[p][q * 2 + 1]);
                        }
                    }
            }
        }
        __syncthreads();
    }

    const int rbase = bm + wm * 32 + (lane >> 2);
    const int cbase = bnl + wn * 64 + (lane & 3) * 2;
#pragma unroll
    for (int mb = 0; mb < 2; ++mb) {
        int r0 = rbase + mb * 16;
#pragma unroll
        for (int nb = 0; nb < 8; ++nb) {
            int col = cbase + nb * 8;
            float bx = 0.f, by = 0.f;
            if (bias) { bx = bias[col]; by = bias[col + 1]; }
            float c0 = acc[mb][nb][0] + bx, c1 = acc[mb][nb][1] + by;
            float c2 = acc[mb][nb][2] + bx, c3 = acc[mb][nb][3] + by;
            if (OUT_HALF) {
                __half* C = (__half*)Csel;
                if (r0 < M) *(__half2*)(C + (size_t)r0 * HID + col) = __floats2half2_rn(c0, c1);
                if (r0 + 8 < M) *(__half2*)(C + (size_t)(r0 + 8) * HID + col) = __floats2half2_rn(c2, c3);
            } else {
                float* C = (float*)Csel;
                if (r0 < M) *(float2*)(C + (size_t)r0 * HID + col) = make_float2(c0, c1);
                if (r0 + 8 < M) *(float2*)(C + (size_t)(r0 + 8) * HID + col) = make_float2(c2, c3);
            }
        }
    }
}

// ---------------- CSR build ----------------
__global__ void zero_cnt(int n) {
    int i = blockIdx.x * blockDim.x + threadIdx.x;
    if (i < n) g_cnt[i] = 0;
}
__global__ void hist_kernel(const int* __restrict__ dst, int E) {
    int e = blockIdx.x * blockDim.x + threadIdx.x;
    if (e < E) atomicAdd(&g_cnt[dst[e]], 1);
}
__global__ void scanA(int n) {
    __shared__ int sd[256];
    int i = blockIdx.x * 256 + threadIdx.x;
    sd[threadIdx.x] = (i < n) ? g_cnt[i] : 0;
    __syncthreads();
#pragma unroll
    for (int d = 128; d > 0; d >>= 1) {
        if (threadIdx.x < d) sd[threadIdx.x] += sd[threadIdx.x + d];
        __syncthreads();
    }
    if (threadIdx.x == 0) g_bsum[blockIdx.x] = sd[0];
}
__global__ void scanB(int nb) {
    __shared__ int sd[256];
    int tid = threadIdx.x;
    int v = (tid < nb) ? g_bsum[tid] : 0;
    sd[tid] = v;
    __syncthreads();
#pragma unroll
    for (int d = 1; d < 256; d <<= 1) {
        int t = (tid >= d) ? sd[tid - d] : 0;
        __syncthreads();
        sd[tid] += t;
        __syncthreads();
    }
    if (tid < nb) g_bsum[tid] = sd[tid] - v;  // exclusive
}
__global__ void scanC(int n) {
    __shared__ int sd[256];
    int tid = threadIdx.x;
    int i = blockIdx.x * 256 + tid;
    int v = (i < n) ? g_cnt[i] : 0;
    sd[tid] = v;
    __syncthreads();
#pragma unroll
    for (int d = 1; d < 256; d <<= 1) {
        int t = (tid >= d) ? sd[tid - d] : 0;
        __syncthreads();
        sd[tid] += t;
        __syncthreads();
    }
    if (i < n) {
        int off = g_bsum[blockIdx.x] + sd[tid] - v;
        g_off[i] = off;
        g_cur[i] = off;
    }
}
__global__ void scatter_kernel(const int* __restrict__ src,
                               const int* __restrict__ dst, int E) {
    int e = blockIdx.x * blockDim.x + threadIdx.x;
    if (e < E) {
        int p = atomicAdd(&g_cur[dst[e]], 1);
        g_esrc[p] = src[e];
    }
}

// ---------------- aggregation: one warp per dst node ----------------
__device__ __forceinline__ float edge_score(const uint4& kk, const float4& q0,
                                            const float4& q1) {
    const __half2* kh = (const __half2*)&kk;
    float2 a = __half22float2(kh[0]), b = __half22float2(kh[1]);
    float2 c = __half22float2(kh[2]), d = __half22float2(kh[3]);
    float p = q0.x * a.x + q0.y * a.y + q0.z * b.x + q0.w * b.y +
              q1.x * c.x + q1.y * c.y + q1.z * d.x + q1.w * d.y;
    p += __shfl_xor_sync(0xffffffffu, p, 1);
    p += __shfl_xor_sync(0xffffffffu, p, 2);
    p *= 0.17677669529663687f;  // 1/sqrt(32)
    p = fminf(5.0f, fmaxf(-5.0f, p));
    return exp2f(p * 1.4426950408889634f);
}
__device__ __forceinline__ void accum_v(float (&acc)[8], float sc, const uint4& vv) {
    const __half2* vh = (const __half2*)&vv;
#pragma unroll
    for (int t = 0; t < 4; ++t) {
        float2 f = __half22float2(vh[t]);
        acc[2 * t] += sc * f.x;
        acc[2 * t + 1] += sc * f.y;
    }
}

__global__ void __launch_bounds__(256) aggregate_kernel(int base, int n) {
    int w = (int)((blockIdx.x * (size_t)blockDim.x + threadIdx.x) >> 5);
    int lane = threadIdx.x & 31;
    if (w >= n) return;
    w += base;
    int beg = g_off[w], deg = g_cnt[w];

    uint4 qq = *(const uint4*)(g_qh + (size_t)w * HID + lane * 8);
    const __half2* qh = (const __half2*)&qq;
    float2 qa = __half22float2(qh[0]), qb = __half22float2(qh[1]);
    float2 qc = __half22float2(qh[2]), qd = __half22float2(qh[3]);
    float4 q0 = make_float4(qa.x, qa.y, qb.x, qb.y);
    float4 q1 = make_float4(qc.x, qc.y, qd.x, qd.y);

    float acc[8] = {0, 0, 0, 0, 0, 0, 0, 0};
    float zacc = 0.f;

    int j = 0;
    for (; j + 4 <= deg; j += 4) {
        int s0 = g_esrc[beg + j + 0];
        int s1 = g_esrc[beg + j + 1];
        int s2 = g_esrc[beg + j + 2];
        int s3 = g_esrc[beg + j + 3];
        uint4 k0 = *(const uint4*)(g_kh + (size_t)s0 * HID + lane * 8);
        uint4 k1 = *(const uint4*)(g_kh + (size_t)s1 * HID + lane * 8);
        uint4 k2 = *(const uint4*)(g_kh + (size_t)s2 * HID + lane * 8);
        uint4 k3 = *(const uint4*)(g_kh + (size_t)s3 * HID + lane * 8);
        uint4 v0 = *(const uint4*)(g_vh + (size_t)s0 * HID + lane * 8);
        uint4 v1 = *(const uint4*)(g_vh + (size_t)s1 * HID + lane * 8);
        uint4 v2 = *(const uint4*)(g_vh + (size_t)s2 * HID + lane * 8);
        uint4 v3 = *(const uint4*)(g_vh + (size_t)s3 * HID + lane * 8);
        float sc0 = edge_score(k0, q0, q1);
        float sc1 = edge_score(k1, q0, q1);
        float sc2 = edge_score(k2, q0, q1);
        float sc3 = edge_score(k3, q0, q1);
        accum_v(acc, sc0, v0);
        accum_v(acc, sc1, v1);
        accum_v(acc, sc2, v2);
        accum_v(acc, sc3, v3);
        zacc += (sc0 + sc1) + (sc2 + sc3);
    }
    for (; j < deg; ++j) {
        int s0 = g_esrc[beg + j];
        uint4 k0 = *(const uint4*)(g_kh + (size_t)s0 * HID + lane * 8);
        uint4 v0 = *(const uint4*)(g_vh + (size_t)s0 * HID + lane * 8);
        float sc0 = edge_score(k0, q0, q1);
        accum_v(acc, sc0, v0);
        zacc += sc0;
    }

    // write normalized wv as fp16 hi/lo
    float inv = 1.0f / zacc;
    uint4 UH, UL;
    uint32_t* uh = (uint32_t*)&UH;
    uint32_t* ul = (uint32_t*)&UL;
#pragma unroll
    for (int t = 0; t < 4; ++t) {
        float a = acc[2 * t] * inv, b = acc[2 * t + 1] * inv;
        __half2 h = __floats2half2_rn(a, b);
        float2 hf = __half22float2(h);
        __half2 l = __floats2half2_rn(a - hf.x, b - hf.y);
        uh[t] = *(uint32_t*)&h;
        ul[t] = *(uint32_t*)&l;
    }
    *(uint4*)(g_ah + (size_t)w * HID + lane * 8) = UH;
    *(uint4*)(g_al + (size_t)w * HID + lane * 8) = UL;
}

// ---------------- launch ----------------
extern "C" void kernel_launch(void* const* d_in, const int* in_sizes, int n_in,
                              void* d_out, int out_size) {
    const float* context = (const float*)d_in[0];
    const float* node    = (const float*)d_in[1];
    const float* Wq      = (const float*)d_in[2];
    const float* bq      = (const float*)d_in[3];
    const float* Wk      = (const float*)d_in[4];
    const float* Wv      = (const float*)d_in[5];
    const float* Wo      = (const float*)d_in[6];
    const float* bo      = (const float*)d_in[7];
    const int*   src     = (const int*)d_in[8];
    const int*   dst     = (const int*)d_in[9];
    float* out = (float*)d_out;

    int Nq = in_sizes[0] / HID;
    int Ns = in_sizes[1] / HID;
    int E  = in_sizes[8];

    __half *qb, *kb, *vb, *ah, *al, *nh, *wt;
    cudaGetSymbolAddress((void**)&qb, g_qh);
    cudaGetSymbolAddress((void**)&kb, g_kh);
    cudaGetSymbolAddress((void**)&vb, g_vh);
    cudaGetSymbolAddress((void**)&ah, g_ah);
    cudaGetSymbolAddress((void**)&al, g_al);
    cudaGetSymbolAddress((void**)&nh, g_nh);
    cudaGetSymbolAddress((void**)&wt, g_wt);

    static bool inited = false;
    static cudaStream_t sG, sC;
    static cudaEvent_t evF, evW, evN, evG, evC, evA0, evO0;
    if (!inited) {
        cudaFuncSetAttribute((const void*)gemm_db<1, true, false>,
                             cudaFuncAttributeMaxDynamicSharedMemorySize, 2 * 2 * BUFB);
        cudaFuncSetAttribute((const void*)gemm_db<1, true, true>,
                             cudaFuncAttributeMaxDynamicSharedMemorySize, 2 * 2 * BUFB);
        cudaFuncSetAttribute((const void*)gemm_db<2, false, false>,
                             cudaFuncAttributeMaxDynamicSharedMemorySize, 2 * 3 * BUFB);
        cudaStreamCreateWithFlags(&sG, cudaStreamNonBlocking);
        cudaStreamCreateWithFlags(&sC, cudaStreamNonBlocking);
        cudaEventCreateWithFlags(&evF, cudaEventDisableTiming);
        cudaEventCreateWithFlags(&evW, cudaEventDisableTiming);
        cudaEventCreateWithFlags(&evN, cudaEventDisableTiming);
        cudaEventCreateWithFlags(&evG, cudaEventDisableTiming);
        cudaEventCreateWithFlags(&evC, cudaEventDisableTiming);
        cudaEventCreateWithFlags(&evA0, cudaEventDisableTiming);
        cudaEventCreateWithFlags(&evO0, cudaEventDisableTiming);
        inited = true;
    }

    dim3 gq((Ns + 127) / 128, 2);
    dim3 gkv((Nq + 127) / 128, 4);  // fused k+v: N=512
    int nb = (Ns + 255) / 256;
    int n4s = Ns * HID / 4, n4q = Nq * HID / 4;

    // fork
    cudaEventRecord(evF, 0);
    cudaStreamWaitEvent(sG, evF, 0);
    cudaStreamWaitEvent(sC, evF, 0);

    // ---- stream sG: weights + node conv + ctx conv + fused kv GEMM ----
    conv_w_all<<<1024, 256, 0, sG>>>(Wq, Wk, Wv, Wo);
    cudaEventRecord(evW, sG);
    conv_hi<<<(n4s + 255) / 256, 256, 0, sG>>>(node, nh, n4s);
    cudaEventRecord(evN, sG);
    conv_hi<<<(n4q + 255) / 256, 256, 0, sG>>>(context, ah, n4q);
    gemm_db<1, true, true><<<gkv, 256, 2 * 2 * BUFB, sG>>>(
        ah, nullptr, wt + 1 * HID * HID, nullptr, kb, vb, Nq);
    cudaEventRecord(evG, sG);

    // ---- stream sC: CSR + q GEMM ----
    zero_cnt<<<nb, 256, 0, sC>>>(Ns);
    hist_kernel<<<(E + 255) / 256, 256, 0, sC>>>(dst, E);
    scanA<<<nb, 256, 0, sC>>>(Ns);
    scanB<<<1, 256, 0, sC>>>(nb);
    scanC<<<nb, 256, 0, sC>>>(Ns);
    scatter_kernel<<<(E + 255) / 256, 256, 0, sC>>>(src, dst, E);
    cudaStreamWaitEvent(sC, evW, 0);
    cudaStreamWaitEvent(sC, evN, 0);
    gemm_db<1, true, false><<<gq, 256, 2 * 2 * BUFB, sC>>>(
        nh, nullptr, wt + 0 * HID * HID, bq, qb, nullptr, Ns);
    cudaEventRecord(evC, sC);

    // ---- join onto default stream ----
    cudaStreamWaitEvent(0, evG, 0);
    cudaStreamWaitEvent(0, evC, 0);

    // ---- aggregation + output projection, 2-chunk pipeline (R8 scheme) ----
    int nblk = (Ns + 127) / 128;
    int c0 = ((nblk + 1) / 2) * 128;
    if (c0 > Ns) c0 = Ns;
    int c1 = Ns - c0;

    aggregate_kernel<<<(c0 + 7) / 8, 256>>>(0, c0);
    cudaEventRecord(evA0, 0);
    if (c1 > 0) aggregate_kernel<<<(c1 + 7) / 8, 256>>>(c0, c1);

    cudaStreamWaitEvent(sG, evA0, 0);
    dim3 g0((c0 + 127) / 128, 2);
    gemm_db<2, false, false><<<g0, 256, 2 * 3 * BUFB, sG>>>(
        ah, al, wt + 3 * HID * HID, bo, out, nullptr, c0);
    cudaEventRecord(evO0, sG);

    if (c1 > 0) {
        dim3 g1((c1 + 127) / 128, 2);
        gemm_db<2, false, false><<<g1, 256, 2 * 3 * BUFB>>>(
            ah + (size_t)c0 * HID, al + (size_t)c0 * HID, wt + 3 * HID * HID, bo,
            out + (size_t)c0 * HID, nullptr, c1);
    }
    cudaStreamWaitEvent(0, evO0, 0);
}

// round 11
// speedup vs baseline: 1.1683x; 1.0796x over previous
#include <cuda_runtime.h>
#include <cuda_fp16.h>
#include <math.h>
#include <cstdint>

#define HID 256
#define NHEAD 8
#define DK 32
#define MAXN 50048
#define MAXE 1048576

// ---------------- device scratch (allocation-free rule) ----------------
__device__ __half g_qh[MAXN * HID];     // q (fp16)
__device__ __half g_kh[MAXN * HID];     // k (fp16)
__device__ __half g_vh[MAXN * HID];     // v (fp16)
__device__ __half g_ah[MAXN * HID];     // ctx hi -> later wv hi
__device__ __half g_nh[MAXN * HID];     // node hi
__device__ __half g_wt[4 * HID * HID];  // Wt fp16 [n][k], 4 slots (q,k,v,o)
// CSR
__device__ int g_cnt[MAXN];
__device__ int g_off[MAXN];
__device__ int g_cur[MAXN];
__device__ int g_esrc[MAXE];
__device__ int g_bsum[256];

// ---------------- helpers ----------------
__device__ __forceinline__ uint32_t smem_u32(const void* p) {
    uint32_t a;
    asm("{ .reg .u64 t; cvta.to.shared.u64 t, %1; cvt.u32.u64 %0, t; }"
        : "=r"(a) : "l"(p));
    return a;
}
__device__ __forceinline__ void ldsm4(uint32_t (&r)[4], uint32_t addr) {
    asm volatile("ldmatrix.sync.aligned.m8n8.x4.shared.b16 {%0,%1,%2,%3}, [%4];"
                 : "=r"(r[0]), "=r"(r[1]), "=r"(r[2]), "=r"(r[3]) : "r"(addr));
}
__device__ __forceinline__ void mma16816h(float (&c)[4], const uint32_t (&a)[4],
                                          uint32_t b0, uint32_t b1) {
    asm volatile(
        "mma.sync.aligned.m16n8k16.row.col.f32.f16.f16.f32 "
        "{%0,%1,%2,%3}, {%4,%5,%6,%7}, {%8,%9}, {%0,%1,%2,%3};"
        : "+f"(c[0]), "+f"(c[1]), "+f"(c[2]), "+f"(c[3])
        : "r"(a[0]), "r"(a[1]), "r"(a[2]), "r"(a[3]), "r"(b0), "r"(b1));
}
__device__ __forceinline__ void cpasync16(uint32_t s, const void* g) {
    asm volatile("cp.async.cg.shared.global [%0], [%1], 16;"
                 :: "r"(s), "l"(g) : "memory");
}
__device__ __forceinline__ void cp_commit() {
    asm volatile("cp.async.commit_group;" ::: "memory");
}
template <int N>
__device__ __forceinline__ void cp_wait() {
    asm volatile("cp.async.wait_group %0;" :: "n"(N) : "memory");
}

// ---------------- conversion kernels ----------------
__global__ void conv_w_all(const float* __restrict__ W0, const float* __restrict__ W1,
                           const float* __restrict__ W2, const float* __restrict__ W3) {
    int idx = blockIdx.x * blockDim.x + threadIdx.x;  // 4*65536
    int slot = idx >> 16;
    int r = idx & 65535;
    int k = r >> 8, n = r & 255;
    const float* W = (slot == 0) ? W0 : (slot == 1) ? W1 : (slot == 2) ? W2 : W3;
    g_wt[slot * HID * HID + n * HID + k] = __float2half_rn(W[k * HID + n]);
}

// fp32 -> fp16 hi only
__global__ void conv_hi(const float* __restrict__ in, __half* __restrict__ hi, int n4) {
    int i = blockIdx.x * blockDim.x + threadIdx.x;
    if (i >= n4) return;
    float4 v = ((const float4*)in)[i];
    ((__half2*)hi)[2 * i] = __floats2half2_rn(v.x, v.y);
    ((__half2*)hi)[2 * i + 1] = __floats2half2_rn(v.z, v.w);
}

// ------- HMMA fp16 GEMM, cp.async double-buffered ------------------------
// C[M,N] = Ah @ Wt^T (+bias). All operands fp16 in global.
// CTA 128x128, 8 warps (4m x 2n), warp tile 32x64, K chunks of 64, 2 stages.
// DUAL: B spans 512 n-rows (two weight slots); cols [0,256)->Cout, [256,512)->Cout2.
#define PADH 72
#define BUFB (128 * PADH * 2)  // 18432 bytes per buffer

template <bool OUT_HALF, bool DUAL>
__global__ void __launch_bounds__(256, 2) gemm_db(
    const __half* __restrict__ Ah, const __half* __restrict__ Bt,
    const float* __restrict__ bias,
    void* __restrict__ Cout, void* __restrict__ Cout2, int M) {
    extern __shared__ char smraw[];
    const uint32_t smb = smem_u32(smraw);
    constexpr int S = 2;  // buffers per stage (A, B)

    const int tid = threadIdx.x, wid = tid >> 5, lane = tid & 31;
    const int bm = blockIdx.x * 128, bn = blockIdx.y * 128;
    const int wm = wid & 3, wn = wid >> 2;

    void* Csel = (DUAL && bn >= 256) ? Cout2 : Cout;
    const int bnl = DUAL ? (bn & 255) : bn;

    const uint32_t aRow = lane & 15, aColOff = (lane >> 4) * 8;
    const uint32_t bg = lane >> 3;
    const uint32_t bRowOff = (bg >> 1) * 8 + (lane & 7), bColOff = (bg & 1) * 8;

    float acc[2][8][4];
#pragma unroll
    for (int mb = 0; mb < 2; ++mb)
#pragma unroll
        for (int nb = 0; nb < 8; ++nb)
#pragma unroll
            for (int t = 0; t < 4; ++t) acc[mb][nb][t] = 0.f;

    auto stage = [&](int c, int s) {
        const int k0 = c * 64;
        const uint32_t sb = smb + s * S * BUFB;
#pragma unroll
        for (int it = 0; it < 4; ++it) {
            int u = tid + it * 256;  // 1024 = 128 rows * 8 vec8
            int row = u >> 3, col8 = u & 7;
            uint32_t so = (uint32_t)(row * PADH + col8 * 8) * 2;
            int gr = bm + row;
            if (gr < M) {
                cpasync16(sb + so, Ah + (size_t)gr * HID + k0 + col8 * 8);
            }
            cpasync16(sb + BUFB + so,
                      Bt + (size_t)(bn + row) * HID + k0 + col8 * 8);
        }
    };

    stage(0, 0);
    cp_commit();
#pragma unroll
    for (int c = 0; c < 4; ++c) {
        if (c < 3) {
            stage(c + 1, (c + 1) & 1);
            cp_commit();
        }
        if (c < 3) cp_wait<1>(); else cp_wait<0>();
        __syncthreads();

        const uint32_t st = smb + (c & 1) * S * BUFB;
#pragma unroll
        for (int kk = 0; kk < 4; ++kk) {
            const uint32_t kb = kk * 16;
            uint32_t ah[2][4];
#pragma unroll
            for (int mb = 0; mb < 2; ++mb) {
                uint32_t aoff = st + ((wm * 32 + mb * 16 + aRow) * PADH + kb + aColOff) * 2;
                ldsm4(ah[mb], aoff);
            }
#pragma unroll
            for (int half = 0; half < 2; ++half) {
                uint32_t bh[2][4];
#pragma unroll
                for (int p = 0; p < 2; ++p) {
                    uint32_t boff = st + BUFB +
                                    ((wn * 64 + half * 32 + p * 16 + bRowOff) * PADH +
                                     kb + bColOff) * 2;
                    ldsm4(bh[p], boff);
                }
#pragma unroll
                for (int p = 0; p < 2; ++p)
#pragma unroll
                    for (int q = 0; q < 2; ++q) {
                        int nb = half * 4 + p * 2 + q;
#pragma unroll
                        for (int mb = 0; mb < 2; ++mb)
                            mma16816h(acc[mb][nb], ah[mb], bh[p][q * 2], bh[p][q * 2 + 1]);
                    }
            }
        }
        __syncthreads();
    }

    const int rbase = bm + wm * 32 + (lane >> 2);
    const int cbase = bnl + wn * 64 + (lane & 3) * 2;
#pragma unroll
    for (int mb = 0; mb < 2; ++mb) {
        int r0 = rbase + mb * 16;
#pragma unroll
        for (int nb = 0; nb < 8; ++nb) {
            int col = cbase + nb * 8;
            float bx = 0.f, by = 0.f;
            if (bias) { bx = bias[col]; by = bias[col + 1]; }
            float c0 = acc[mb][nb][0] + bx, c1 = acc[mb][nb][1] + by;
            float c2 = acc[mb][nb][2] + bx, c3 = acc[mb][nb][3] + by;
            if (OUT_HALF) {
                __half* C = (__half*)Csel;
                if (r0 < M) *(__half2*)(C + (size_t)r0 * HID + col) = __floats2half2_rn(c0, c1);
                if (r0 + 8 < M) *(__half2*)(C + (size_t)(r0 + 8) * HID + col) = __floats2half2_rn(c2, c3);
            } else {
                float* C = (float*)Csel;
                if (r0 < M) *(float2*)(C + (size_t)r0 * HID + col) = make_float2(c0, c1);
                if (r0 + 8 < M) *(float2*)(C + (size_t)(r0 + 8) * HID + col) = make_float2(c2, c3);
            }
        }
    }
}

// ---------------- CSR build ----------------
__global__ void zero_cnt(int n) {
    int i = blockIdx.x * blockDim.x + threadIdx.x;
    if (i < n) g_cnt[i] = 0;
}
__global__ void hist_kernel(const int* __restrict__ dst, int E) {
    int e = blockIdx.x * blockDim.x + threadIdx.x;
    if (e < E) atomicAdd(&g_cnt[dst[e]], 1);
}
__global__ void scanA(int n) {
    __shared__ int sd[256];
    int i = blockIdx.x * 256 + threadIdx.x;
    sd[threadIdx.x] = (i < n) ? g_cnt[i] : 0;
    __syncthreads();
#pragma unroll
    for (int d = 128; d > 0; d >>= 1) {
        if (threadIdx.x < d) sd[threadIdx.x] += sd[threadIdx.x + d];
        __syncthreads();
    }
    if (threadIdx.x == 0) g_bsum[blockIdx.x] = sd[0];
}
__global__ void scanB(int nb) {
    __shared__ int sd[256];
    int tid = threadIdx.x;
    int v = (tid < nb) ? g_bsum[tid] : 0;
    sd[tid] = v;
    __syncthreads();
#pragma unroll
    for (int d = 1; d < 256; d <<= 1) {
        int t = (tid >= d) ? sd[tid - d] : 0;
        __syncthreads();
        sd[tid] += t;
        __syncthreads();
    }
    if (tid < nb) g_bsum[tid] = sd[tid] - v;  // exclusive
}
__global__ void scanC(int n) {
    __shared__ int sd[256];
    int tid = threadIdx.x;
    int i = blockIdx.x * 256 + tid;
    int v = (i < n) ? g_cnt[i] : 0;
    sd[tid] = v;
    __syncthreads();
#pragma unroll
    for (int d = 1; d < 256; d <<= 1) {
        int t = (tid >= d) ? sd[tid - d] : 0;
        __syncthreads();
        sd[tid] += t;
        __syncthreads();
    }
    if (i < n) {
        int off = g_bsum[blockIdx.x] + sd[tid] - v;
        g_off[i] = off;
        g_cur[i] = off;
    }
}
__global__ void scatter_kernel(const int* __restrict__ src,
                               const int* __restrict__ dst, int E) {
    int e = blockIdx.x * blockDim.x + threadIdx.x;
    if (e < E) {
        int p = atomicAdd(&g_cur[dst[e]], 1);
        g_esrc[p] = src[e];
    }
}

// ---------------- aggregation: one warp per dst node ----------------
__device__ __forceinline__ float edge_score(const uint4& kk, const float4& q0,
                                            const float4& q1) {
    const __half2* kh = (const __half2*)&kk;
    float2 a = __half22float2(kh[0]), b = __half22float2(kh[1]);
    float2 c = __half22float2(kh[2]), d = __half22float2(kh[3]);
    float p = q0.x * a.x + q0.y * a.y + q0.z * b.x + q0.w * b.y +
              q1.x * c.x + q1.y * c.y + q1.z * d.x + q1.w * d.y;
    p += __shfl_xor_sync(0xffffffffu, p, 1);
    p += __shfl_xor_sync(0xffffffffu, p, 2);
    p *= 0.17677669529663687f;  // 1/sqrt(32)
    p = fminf(5.0f, fmaxf(-5.0f, p));
    return exp2f(p * 1.4426950408889634f);
}
__device__ __forceinline__ void accum_v(float (&acc)[8], float sc, const uint4& vv) {
    const __half2* vh = (const __half2*)&vv;
#pragma unroll
    for (int t = 0; t < 4; ++t) {
        float2 f = __half22float2(vh[t]);
        acc[2 * t] += sc * f.x;
        acc[2 * t + 1] += sc * f.y;
    }
}

__global__ void __launch_bounds__(256) aggregate_kernel(int base, int n) {
    int w = (int)((blockIdx.x * (size_t)blockDim.x + threadIdx.x) >> 5);
    int lane = threadIdx.x & 31;
    if (w >= n) return;
    w += base;
    int beg = g_off[w], deg = g_cnt[w];

    uint4 qq = *(const uint4*)(g_qh + (size_t)w * HID + lane * 8);
    const __half2* qh = (const __half2*)&qq;
    float2 qa = __half22float2(qh[0]), qb = __half22float2(qh[1]);
    float2 qc = __half22float2(qh[2]), qd = __half22float2(qh[3]);
    float4 q0 = make_float4(qa.x, qa.y, qb.x, qb.y);
    float4 q1 = make_float4(qc.x, qc.y, qd.x, qd.y);

    float acc[8] = {0, 0, 0, 0, 0, 0, 0, 0};
    float zacc = 0.f;

    int j = 0;
    for (; j + 4 <= deg; j += 4) {
        int s0 = g_esrc[beg + j + 0];
        int s1 = g_esrc[beg + j + 1];
        int s2 = g_esrc[beg + j + 2];
        int s3 = g_esrc[beg + j + 3];
        uint4 k0 = *(const uint4*)(g_kh + (size_t)s0 * HID + lane * 8);
        uint4 k1 = *(const uint4*)(g_kh + (size_t)s1 * HID + lane * 8);
        uint4 k2 = *(const uint4*)(g_kh + (size_t)s2 * HID + lane * 8);
        uint4 k3 = *(const uint4*)(g_kh + (size_t)s3 * HID + lane * 8);
        uint4 v0 = *(const uint4*)(g_vh + (size_t)s0 * HID + lane * 8);
        uint4 v1 = *(const uint4*)(g_vh + (size_t)s1 * HID + lane * 8);
        uint4 v2 = *(const uint4*)(g_vh + (size_t)s2 * HID + lane * 8);
        uint4 v3 = *(const uint4*)(g_vh + (size_t)s3 * HID + lane * 8);
        float sc0 = edge_score(k0, q0, q1);
        float sc1 = edge_score(k1, q0, q1);
        float sc2 = edge_score(k2, q0, q1);
        float sc3 = edge_score(k3, q0, q1);
        accum_v(acc, sc0, v0);
        accum_v(acc, sc1, v1);
        accum_v(acc, sc2, v2);
        accum_v(acc, sc3, v3);
        zacc += (sc0 + sc1) + (sc2 + sc3);
    }
    for (; j < deg; ++j) {
        int s0 = g_esrc[beg + j];
        uint4 k0 = *(const uint4*)(g_kh + (size_t)s0 * HID + lane * 8);
        uint4 v0 = *(const uint4*)(g_vh + (size_t)s0 * HID + lane * 8);
        float sc0 = edge_score(k0, q0, q1);
        accum_v(acc, sc0, v0);
        zacc += sc0;
    }

    // write normalized wv as fp16 (hi only — out-GEMM is NPROD=1)
    float inv = 1.0f / zacc;
    uint4 UH;
    uint32_t* uh = (uint32_t*)&UH;
#pragma unroll
    for (int t = 0; t < 4; ++t) {
        __half2 h = __floats2half2_rn(acc[2 * t] * inv, acc[2 * t + 1] * inv);
        uh[t] = *(uint32_t*)&h;
    }
    *(uint4*)(g_ah + (size_t)w * HID + lane * 8) = UH;
}

// ---------------- launch ----------------
extern "C" void kernel_launch(void* const* d_in, const int* in_sizes, int n_in,
                              void* d_out, int out_size) {
    const float* context = (const float*)d_in[0];
    const float* node    = (const float*)d_in[1];
    const float* Wq      = (const float*)d_in[2];
    const float* bq      = (const float*)d_in[3];
    const float* Wk      = (const float*)d_in[4];
    const float* Wv      = (const float*)d_in[5];
    const float* Wo      = (const float*)d_in[6];
    const float* bo      = (const float*)d_in[7];
    const int*   src     = (const int*)d_in[8];
    const int*   dst     = (const int*)d_in[9];
    float* out = (float*)d_out;

    int Nq = in_sizes[0] / HID;
    int Ns = in_sizes[1] / HID;
    int E  = in_sizes[8];

    __half *qb, *kb, *vb, *ah, *nh, *wt;
    cudaGetSymbolAddress((void**)&qb, g_qh);
    cudaGetSymbolAddress((void**)&kb, g_kh);
    cudaGetSymbolAddress((void**)&vb, g_vh);
    cudaGetSymbolAddress((void**)&ah, g_ah);
    cudaGetSymbolAddress((void**)&nh, g_nh);
    cudaGetSymbolAddress((void**)&wt, g_wt);

    static bool inited = false;
    static cudaStream_t sG, sC;
    static cudaEvent_t evF, evW, evN, evG, evC, evA0, evO0;
    if (!inited) {
        cudaFuncSetAttribute((const void*)gemm_db<true, false>,
                             cudaFuncAttributeMaxDynamicSharedMemorySize, 2 * 2 * BUFB);
        cudaFuncSetAttribute((const void*)gemm_db<true, true>,
                             cudaFuncAttributeMaxDynamicSharedMemorySize, 2 * 2 * BUFB);
        cudaFuncSetAttribute((const void*)gemm_db<false, false>,
                             cudaFuncAttributeMaxDynamicSharedMemorySize, 2 * 2 * BUFB);
        cudaStreamCreateWithFlags(&sG, cudaStreamNonBlocking);
        cudaStreamCreateWithFlags(&sC, cudaStreamNonBlocking);
        cudaEventCreateWithFlags(&evF, cudaEventDisableTiming);
        cudaEventCreateWithFlags(&evW, cudaEventDisableTiming);
        cudaEventCreateWithFlags(&evN, cudaEventDisableTiming);
        cudaEventCreateWithFlags(&evG, cudaEventDisableTiming);
        cudaEventCreateWithFlags(&evC, cudaEventDisableTiming);
        cudaEventCreateWithFlags(&evA0, cudaEventDisableTiming);
        cudaEventCreateWithFlags(&evO0, cudaEventDisableTiming);
        inited = true;
    }

    dim3 gq((Ns + 127) / 128, 2);
    dim3 gkv((Nq + 127) / 128, 4);  // fused k+v: N=512
    int nb = (Ns + 255) / 256;
    int n4s = Ns * HID / 4, n4q = Nq * HID / 4;

    // fork
    cudaEventRecord(evF, 0);
    cudaStreamWaitEvent(sG, evF, 0);
    cudaStreamWaitEvent(sC, evF, 0);

    // ---- stream sG: weights + node conv + ctx conv + fused kv GEMM ----
    conv_w_all<<<1024, 256, 0, sG>>>(Wq, Wk, Wv, Wo);
    cudaEventRecord(evW, sG);
    conv_hi<<<(n4s + 255) / 256, 256, 0, sG>>>(node, nh, n4s);
    cudaEventRecord(evN, sG);
    conv_hi<<<(n4q + 255) / 256, 256, 0, sG>>>(context, ah, n4q);
    gemm_db<true, true><<<gkv, 256, 2 * 2 * BUFB, sG>>>(
        ah, wt + 1 * HID * HID, nullptr, kb, vb, Nq);
    cudaEventRecord(evG, sG);

    // ---- stream sC: CSR + q GEMM ----
    zero_cnt<<<nb, 256, 0, sC>>>(Ns);
    hist_kernel<<<(E + 255) / 256, 256, 0, sC>>>(dst, E);
    scanA<<<nb, 256, 0, sC>>>(Ns);
    scanB<<<1, 256, 0, sC>>>(nb);
    scanC<<<nb, 256, 0, sC>>>(Ns);
    scatter_kernel<<<(E + 255) / 256, 256, 0, sC>>>(src, dst, E);
    cudaStreamWaitEvent(sC, evW, 0);
    cudaStreamWaitEvent(sC, evN, 0);
    gemm_db<true, false><<<gq, 256, 2 * 2 * BUFB, sC>>>(
        nh, wt + 0 * HID * HID, bq, qb, nullptr, Ns);
    cudaEventRecord(evC, sC);

    // ---- join onto default stream ----
    cudaStreamWaitEvent(0, evG, 0);
    cudaStreamWaitEvent(0, evC, 0);

    // ---- aggregation + output projection, asymmetric 60/40 pipeline ----
    int nblk = (Ns + 127) / 128;
    int c0 = ((nblk * 3 + 4) / 5) * 128;  // ~60% rounded to tile
    if (c0 > Ns) c0 = Ns;
    int c1 = Ns - c0;

    aggregate_kernel<<<(c0 + 7) / 8, 256>>>(0, c0);
    cudaEventRecord(evA0, 0);
    if (c1 > 0) aggregate_kernel<<<(c1 + 7) / 8, 256>>>(c0, c1);

    cudaStreamWaitEvent(sG, evA0, 0);
    dim3 g0((c0 + 127) / 128, 2);
    gemm_db<false, false><<<g0, 256, 2 * 2 * BUFB, sG>>>(
        ah, wt + 3 * HID * HID, bo, out, nullptr, c0);
    cudaEventRecord(evO0, sG);

    if (c1 > 0) {
        dim3 g1((c1 + 127) / 128, 2);
        gemm_db<false, false><<<g1, 256, 2 * 2 * BUFB>>>(
            ah + (size_t)c0 * HID, wt + 3 * HID * HID, bo,
            out + (size_t)c0 * HID, nullptr, c1);
    }
    cudaStreamWaitEvent(0, evO0, 0);
}

// round 12
// speedup vs baseline: 1.1891x; 1.0177x over previous
#include <cuda_runtime.h>
#include <cuda_fp16.h>
#include <math.h>
#include <cstdint>

#define HID 256
#define NHEAD 8
#define DK 32
#define MAXN 50048
#define MAXE 1048576

// ---------------- device scratch (allocation-free rule) ----------------
__device__ __half g_qh[MAXN * HID];     // q (fp16)
__device__ __half g_kh[MAXN * HID];     // k (fp16)
__device__ __half g_vh[MAXN * HID];     // v (fp16)
__device__ __half g_ah[MAXN * HID];     // ctx hi -> later wv hi
__device__ __half g_nh[MAXN * HID];     // node hi
__device__ __half g_wt[4 * HID * HID];  // Wt fp16 [n][k], 4 slots (q,k,v,o)
// CSR
__device__ int g_cnt[MAXN];
__device__ int g_off[MAXN];
__device__ int g_cur[MAXN];
__device__ int g_esrc[MAXE];
__device__ int g_bsum[256];

// ---------------- helpers ----------------
__device__ __forceinline__ uint32_t smem_u32(const void* p) {
    uint32_t a;
    asm("{ .reg .u64 t; cvta.to.shared.u64 t, %1; cvt.u32.u64 %0, t; }"
        : "=r"(a) : "l"(p));
    return a;
}
__device__ __forceinline__ void ldsm4(uint32_t (&r)[4], uint32_t addr) {
    asm volatile("ldmatrix.sync.aligned.m8n8.x4.shared.b16 {%0,%1,%2,%3}, [%4];"
                 : "=r"(r[0]), "=r"(r[1]), "=r"(r[2]), "=r"(r[3]) : "r"(addr));
}
__device__ __forceinline__ void mma16816h(float (&c)[4], const uint32_t (&a)[4],
                                          uint32_t b0, uint32_t b1) {
    asm volatile(
        "mma.sync.aligned.m16n8k16.row.col.f32.f16.f16.f32 "
        "{%0,%1,%2,%3}, {%4,%5,%6,%7}, {%8,%9}, {%0,%1,%2,%3};"
        : "+f"(c[0]), "+f"(c[1]), "+f"(c[2]), "+f"(c[3])
        : "r"(a[0]), "r"(a[1]), "r"(a[2]), "r"(a[3]), "r"(b0), "r"(b1));
}
__device__ __forceinline__ void cpasync16(uint32_t s, const void* g) {
    asm volatile("cp.async.cg.shared.global [%0], [%1], 16;"
                 :: "r"(s), "l"(g) : "memory");
}
__device__ __forceinline__ void cp_commit() {
    asm volatile("cp.async.commit_group;" ::: "memory");
}
template <int N>
__device__ __forceinline__ void cp_wait() {
    asm volatile("cp.async.wait_group %0;" :: "n"(N) : "memory");
}

// ---------------- conversion kernels ----------------
__global__ void conv_w_all(const float* __restrict__ W0, const float* __restrict__ W1,
                           const float* __restrict__ W2, const float* __restrict__ W3) {
    int idx = blockIdx.x * blockDim.x + threadIdx.x;  // 4*65536
    int slot = idx >> 16;
    int r = idx & 65535;
    int k = r >> 8, n = r & 255;
    const float* W = (slot == 0) ? W0 : (slot == 1) ? W1 : (slot == 2) ? W2 : W3;
    g_wt[slot * HID * HID + n * HID + k] = __float2half_rn(W[k * HID + n]);
}

// fp32 -> fp16 hi only
__global__ void conv_hi(const float* __restrict__ in, __half* __restrict__ hi, int n4) {
    int i = blockIdx.x * blockDim.x + threadIdx.x;
    if (i >= n4) return;
    float4 v = ((const float4*)in)[i];
    ((__half2*)hi)[2 * i] = __floats2half2_rn(v.x, v.y);
    ((__half2*)hi)[2 * i + 1] = __floats2half2_rn(v.z, v.w);
}

// ------- HMMA fp16 GEMM, cp.async 3-stage pipeline -----------------------
// C[M,N] = Ah @ Wt^T (+bias). All operands fp16 in global.
// CTA 128x128, 8 warps (4m x 2n), warp tile 32x64, K chunks of 64.
// 3 stages, ONE __syncthreads per chunk: the stage issue sits right after
// the barrier, so every warp has finished the mma that last read the
// target buffer (buffer (c+2)%3 was last read in chunk c-1).
// DUAL: B spans 512 n-rows (two weight slots); cols [0,256)->Cout, else Cout2.
#define PADH 72
#define BUFB (128 * PADH * 2)        // 18432 bytes per buffer
#define SM_G (3 * 2 * BUFB)          // 110592 bytes (3 stages x {A,B})

template <bool OUT_HALF, bool DUAL>
__global__ void __launch_bounds__(256, 2) gemm_db(
    const __half* __restrict__ Ah, const __half* __restrict__ Bt,
    const float* __restrict__ bias,
    void* __restrict__ Cout, void* __restrict__ Cout2, int M) {
    extern __shared__ char smraw[];
    const uint32_t smb = smem_u32(smraw);

    const int tid = threadIdx.x, wid = tid >> 5, lane = tid & 31;
    const int bm = blockIdx.x * 128, bn = blockIdx.y * 128;
    const int wm = wid & 3, wn = wid >> 2;

    void* Csel = (DUAL && bn >= 256) ? Cout2 : Cout;
    const int bnl = DUAL ? (bn & 255) : bn;

    const uint32_t aRow = lane & 15, aColOff = (lane >> 4) * 8;
    const uint32_t bg = lane >> 3;
    const uint32_t bRowOff = (bg >> 1) * 8 + (lane & 7), bColOff = (bg & 1) * 8;

    float acc[2][8][4];
#pragma unroll
    for (int mb = 0; mb < 2; ++mb)
#pragma unroll
        for (int nb = 0; nb < 8; ++nb)
#pragma unroll
            for (int t = 0; t < 4; ++t) acc[mb][nb][t] = 0.f;

    auto stage = [&](int c, int s) {
        const int k0 = c * 64;
        const uint32_t sb = smb + s * 2 * BUFB;
#pragma unroll
        for (int it = 0; it < 4; ++it) {
            int u = tid + it * 256;  // 1024 = 128 rows * 8 vec8
            int row = u >> 3, col8 = u & 7;
            uint32_t so = (uint32_t)(row * PADH + col8 * 8) * 2;
            int gr = bm + row;
            if (gr < M) {
                cpasync16(sb + so, Ah + (size_t)gr * HID + k0 + col8 * 8);
            }
            cpasync16(sb + BUFB + so,
                      Bt + (size_t)(bn + row) * HID + k0 + col8 * 8);
        }
    };

    stage(0, 0);
    cp_commit();
    stage(1, 1);
    cp_commit();
#pragma unroll
    for (int c = 0; c < 4; ++c) {
        if (c < 3) cp_wait<1>(); else cp_wait<0>();
        __syncthreads();
        if (c + 2 < 4) {
            stage(c + 2, (c + 2) % 3);
            cp_commit();
        }

        const uint32_t st = smb + (c % 3) * 2 * BUFB;
#pragma unroll
        for (int kk = 0; kk < 4; ++kk) {
            const uint32_t kb = kk * 16;
            uint32_t ah[2][4];
#pragma unroll
            for (int mb = 0; mb < 2; ++mb) {
                uint32_t aoff = st + ((wm * 32 + mb * 16 + aRow) * PADH + kb + aColOff) * 2;
                ldsm4(ah[mb], aoff);
            }
#pragma unroll
            for (int half = 0; half < 2; ++half) {
                uint32_t bh[2][4];
#pragma unroll
                for (int p = 0; p < 2; ++p) {
                    uint32_t boff = st + BUFB +
                                    ((wn * 64 + half * 32 + p * 16 + bRowOff) * PADH +
                                     kb + bColOff) * 2;
                    ldsm4(bh[p], boff);
                }
#pragma unroll
                for (int p = 0; p < 2; ++p)
#pragma unroll
                    for (int q = 0; q < 2; ++q) {
                        int nb = half * 4 + p * 2 + q;
#pragma unroll
                        for (int mb = 0; mb < 2; ++mb)
                            mma16816h(acc[mb][nb], ah[mb], bh[p][q * 2], bh[p][q * 2 + 1]);
                    }
            }
        }
    }

    const int rbase = bm + wm * 32 + (lane >> 2);
    const int cbase = bnl + wn * 64 + (lane & 3) * 2;
#pragma unroll
    for (int mb = 0; mb < 2; ++mb) {
        int r0 = rbase + mb * 16;
#pragma unroll
        for (int nb = 0; nb < 8; ++nb) {
            int col = cbase + nb * 8;
            float bx = 0.f, by = 0.f;
            if (bias) { bx = bias[col]; by = bias[col + 1]; }
            float c0 = acc[mb][nb][0] + bx, c1 = acc[mb][nb][1] + by;
            float c2 = acc[mb][nb][2] + bx, c3 = acc[mb][nb][3] + by;
            if (OUT_HALF) {
                __half* C = (__half*)Csel;
                if (r0 < M) *(__half2*)(C + (size_t)r0 * HID + col) = __floats2half2_rn(c0, c1);
                if (r0 + 8 < M) *(__half2*)(C + (size_t)(r0 + 8) * HID + col) = __floats2half2_rn(c2, c3);
            } else {
                float* C = (float*)Csel;
                if (r0 < M) *(float2*)(C + (size_t)r0 * HID + col) = make_float2(c0, c1);
                if (r0 + 8 < M) *(float2*)(C + (size_t)(r0 + 8) * HID + col) = make_float2(c2, c3);
            }
        }
    }
}

// ---------------- CSR build ----------------
__global__ void zero_cnt(int n) {
    int i = blockIdx.x * blockDim.x + threadIdx.x;
    if (i < n) g_cnt[i] = 0;
}
__global__ void hist_kernel(const int* __restrict__ dst, int E) {
    int e = blockIdx.x * blockDim.x + threadIdx.x;
    if (e < E) atomicAdd(&g_cnt[dst[e]], 1);
}
__global__ void scanA(int n) {
    __shared__ int sd[256];
    int i = blockIdx.x * 256 + threadIdx.x;
    sd[threadIdx.x] = (i < n) ? g_cnt[i] : 0;
    __syncthreads();
#pragma unroll
    for (int d = 128; d > 0; d >>= 1) {
        if (threadIdx.x < d) sd[threadIdx.x] += sd[threadIdx.x + d];
        __syncthreads();
    }
    if (threadIdx.x == 0) g_bsum[blockIdx.x] = sd[0];
}
__global__ void scanB(int nb) {
    __shared__ int sd[256];
    int tid = threadIdx.x;
    int v = (tid < nb) ? g_bsum[tid] : 0;
    sd[tid] = v;
    __syncthreads();
#pragma unroll
    for (int d = 1; d < 256; d <<= 1) {
        int t = (tid >= d) ? sd[tid - d] : 0;
        __syncthreads();
        sd[tid] += t;
        __syncthreads();
    }
    if (tid < nb) g_bsum[tid] = sd[tid] - v;  // exclusive
}
__global__ void scanC(int n) {
    __shared__ int sd[256];
    int tid = threadIdx.x;
    int i = blockIdx.x * 256 + tid;
    int v = (i < n) ? g_cnt[i] : 0;
    sd[tid] = v;
    __syncthreads();
#pragma unroll
    for (int d = 1; d < 256; d <<= 1) {
        int t = (tid >= d) ? sd[tid - d] : 0;
        __syncthreads();
        sd[tid] += t;
        __syncthreads();
    }
    if (i < n) {
        int off = g_bsum[blockIdx.x] + sd[tid] - v;
        g_off[i] = off;
        g_cur[i] = off;
    }
}
__global__ void scatter_kernel(const int* __restrict__ src,
                               const int* __restrict__ dst, int E) {
    int e = blockIdx.x * blockDim.x + threadIdx.x;
    if (e < E) {
        int p = atomicAdd(&g_cur[dst[e]], 1);
        g_esrc[p] = src[e];
    }
}

// ---------------- aggregation: one warp per dst node ----------------
__device__ __forceinline__ float edge_score(const uint4& kk, const float4& q0,
                                            const float4& q1) {
    const __half2* kh = (const __half2*)&kk;
    float2 a = __half22float2(kh[0]), b = __half22float2(kh[1]);
    float2 c = __half22float2(kh[2]), d = __half22float2(kh[3]);
    float p = q0.x * a.x + q0.y * a.y + q0.z * b.x + q0.w * b.y +
              q1.x * c.x + q1.y * c.y + q1.z * d.x + q1.w * d.y;
    p += __shfl_xor_sync(0xffffffffu, p, 1);
    p += __shfl_xor_sync(0xffffffffu, p, 2);
    p *= 0.17677669529663687f;  // 1/sqrt(32)
    p = fminf(5.0f, fmaxf(-5.0f, p));
    return exp2f(p * 1.4426950408889634f);
}
__device__ __forceinline__ void accum_v(float (&acc)[8], float sc, const uint4& vv) {
    const __half2* vh = (const __half2*)&vv;
#pragma unroll
    for (int t = 0; t < 4; ++t) {
        float2 f = __half22float2(vh[t]);
        acc[2 * t] += sc * f.x;
        acc[2 * t + 1] += sc * f.y;
    }
}

__global__ void __launch_bounds__(256) aggregate_kernel(int base, int n) {
    int w = (int)((blockIdx.x * (size_t)blockDim.x + threadIdx.x) >> 5);
    int lane = threadIdx.x & 31;
    if (w >= n) return;
    w += base;
    int beg = g_off[w], deg = g_cnt[w];

    uint4 qq = *(const uint4*)(g_qh + (size_t)w * HID + lane * 8);
    const __half2* qh = (const __half2*)&qq;
    float2 qa = __half22float2(qh[0]), qb = __half22float2(qh[1]);
    float2 qc = __half22float2(qh[2]), qd = __half22float2(qh[3]);
    float4 q0 = make_float4(qa.x, qa.y, qb.x, qb.y);
    float4 q1 = make_float4(qc.x, qc.y, qd.x, qd.y);

    float acc[8] = {0, 0, 0, 0, 0, 0, 0, 0};
    float zacc = 0.f;

    int j = 0;
    for (; j + 4 <= deg; j += 4) {
        int s0 = g_esrc[beg + j + 0];
        int s1 = g_esrc[beg + j + 1];
        int s2 = g_esrc[beg + j + 2];
        int s3 = g_esrc[beg + j + 3];
        uint4 k0 = *(const uint4*)(g_kh + (size_t)s0 * HID + lane * 8);
        uint4 k1 = *(const uint4*)(g_kh + (size_t)s1 * HID + lane * 8);
        uint4 k2 = *(const uint4*)(g_kh + (size_t)s2 * HID + lane * 8);
        uint4 k3 = *(const uint4*)(g_kh + (size_t)s3 * HID + lane * 8);
        uint4 v0 = *(const uint4*)(g_vh + (size_t)s0 * HID + lane * 8);
        uint4 v1 = *(const uint4*)(g_vh + (size_t)s1 * HID + lane * 8);
        uint4 v2 = *(const uint4*)(g_vh + (size_t)s2 * HID + lane * 8);
        uint4 v3 = *(const uint4*)(g_vh + (size_t)s3 * HID + lane * 8);
        float sc0 = edge_score(k0, q0, q1);
        float sc1 = edge_score(k1, q0, q1);
        float sc2 = edge_score(k2, q0, q1);
        float sc3 = edge_score(k3, q0, q1);
        accum_v(acc, sc0, v0);
        accum_v(acc, sc1, v1);
        accum_v(acc, sc2, v2);
        accum_v(acc, sc3, v3);
        zacc += (sc0 + sc1) + (sc2 + sc3);
    }
    for (; j < deg; ++j) {
        int s0 = g_esrc[beg + j];
        uint4 k0 = *(const uint4*)(g_kh + (size_t)s0 * HID + lane * 8);
        uint4 v0 = *(const uint4*)(g_vh + (size_t)s0 * HID + lane * 8);
        float sc0 = edge_score(k0, q0, q1);
        accum_v(acc, sc0, v0);
        zacc += sc0;
    }

    // write normalized wv as fp16 (hi only — out-GEMM is NPROD=1)
    float inv = 1.0f / zacc;
    uint4 UH;
    uint32_t* uh = (uint32_t*)&UH;
#pragma unroll
    for (int t = 0; t < 4; ++t) {
        __half2 h = __floats2half2_rn(acc[2 * t] * inv, acc[2 * t + 1] * inv);
        uh[t] = *(uint32_t*)&h;
    }
    *(uint4*)(g_ah + (size_t)w * HID + lane * 8) = UH;
}

// ---------------- launch ----------------
extern "C" void kernel_launch(void* const* d_in, const int* in_sizes, int n_in,
                              void* d_out, int out_size) {
    const float* context = (const float*)d_in[0];
    const float* node    = (const float*)d_in[1];
    const float* Wq      = (const float*)d_in[2];
    const float* bq      = (const float*)d_in[3];
    const float* Wk      = (const float*)d_in[4];
    const float* Wv      = (const float*)d_in[5];
    const float* Wo      = (const float*)d_in[6];
    const float* bo      = (const float*)d_in[7];
    const int*   src     = (const int*)d_in[8];
    const int*   dst     = (const int*)d_in[9];
    float* out = (float*)d_out;

    int Nq = in_sizes[0] / HID;
    int Ns = in_sizes[1] / HID;
    int E  = in_sizes[8];

    __half *qb, *kb, *vb, *ah, *nh, *wt;
    cudaGetSymbolAddress((void**)&qb, g_qh);
    cudaGetSymbolAddress((void**)&kb, g_kh);
    cudaGetSymbolAddress((void**)&vb, g_vh);
    cudaGetSymbolAddress((void**)&ah, g_ah);
    cudaGetSymbolAddress((void**)&nh, g_nh);
    cudaGetSymbolAddress((void**)&wt, g_wt);

    static bool inited = false;
    static cudaStream_t sG, sC;
    static cudaEvent_t evF, evW, evG, evC, evA0, evO0;
    if (!inited) {
        cudaFuncSetAttribute((const void*)gemm_db<true, false>,
                             cudaFuncAttributeMaxDynamicSharedMemorySize, SM_G);
        cudaFuncSetAttribute((const void*)gemm_db<true, true>,
                             cudaFuncAttributeMaxDynamicSharedMemorySize, SM_G);
        cudaFuncSetAttribute((const void*)gemm_db<false, false>,
                             cudaFuncAttributeMaxDynamicSharedMemorySize, SM_G);
        cudaStreamCreateWithFlags(&sG, cudaStreamNonBlocking);
        cudaStreamCreateWithFlags(&sC, cudaStreamNonBlocking);
        cudaEventCreateWithFlags(&evF, cudaEventDisableTiming);
        cudaEventCreateWithFlags(&evW, cudaEventDisableTiming);
        cudaEventCreateWithFlags(&evG, cudaEventDisableTiming);
        cudaEventCreateWithFlags(&evC, cudaEventDisableTiming);
        cudaEventCreateWithFlags(&evA0, cudaEventDisableTiming);
        cudaEventCreateWithFlags(&evO0, cudaEventDisableTiming);
        inited = true;
    }

    dim3 gq((Ns + 127) / 128, 2);
    dim3 gkv((Nq + 127) / 128, 4);  // fused k+v: N=512
    int nb = (Ns + 255) / 256;
    int n4s = Ns * HID / 4, n4q = Nq * HID / 4;

    // fork
    cudaEventRecord(evF, 0);
    cudaStreamWaitEvent(sG, evF, 0);
    cudaStreamWaitEvent(sC, evF, 0);

    // ---- stream sG: weights + ctx conv + fused kv GEMM ----
    conv_w_all<<<1024, 256, 0, sG>>>(Wq, Wk, Wv, Wo);
    cudaEventRecord(evW, sG);
    conv_hi<<<(n4q + 255) / 256, 256, 0, sG>>>(context, ah, n4q);
    gemm_db<true, true><<<gkv, 256, SM_G, sG>>>(
        ah, wt + 1 * HID * HID, nullptr, kb, vb, Nq);
    cudaEventRecord(evG, sG);

    // ---- stream sC: CSR + node conv + q GEMM ----
    zero_cnt<<<nb, 256, 0, sC>>>(Ns);
    hist_kernel<<<(E + 255) / 256, 256, 0, sC>>>(dst, E);
    scanA<<<nb, 256, 0, sC>>>(Ns);
    scanB<<<1, 256, 0, sC>>>(nb);
    scanC<<<nb, 256, 0, sC>>>(Ns);
    scatter_kernel<<<(E + 255) / 256, 256, 0, sC>>>(src, dst, E);
    conv_hi<<<(n4s + 255) / 256, 256, 0, sC>>>(node, nh, n4s);
    cudaStreamWaitEvent(sC, evW, 0);
    gemm_db<true, false><<<gq, 256, SM_G, sC>>>(
        nh, wt + 0 * HID * HID, bq, qb, nullptr, Ns);
    cudaEventRecord(evC, sC);

    // ---- join onto default stream ----
    cudaStreamWaitEvent(0, evG, 0);
    cudaStreamWaitEvent(0, evC, 0);

    // ---- aggregation + output projection, asymmetric ~70/30 pipeline ----
    int nblk = (Ns + 127) / 128;
    int c0 = ((nblk * 7 + 9) / 10) * 128;  // ~70% rounded to tile
    if (c0 > Ns) c0 = Ns;
    int c1 = Ns - c0;

    aggregate_kernel<<<(c0 + 7) / 8, 256>>>(0, c0);
    cudaEventRecord(evA0, 0);
    if (c1 > 0) aggregate_kernel<<<(c1 + 7) / 8, 256>>>(c0, c1);

    cudaStreamWaitEvent(sG, evA0, 0);
    dim3 g0((c0 + 127) / 128, 2);
    gemm_db<false, false><<<g0, 256, SM_G, sG>>>(
        ah, wt + 3 * HID * HID, bo, out, nullptr, c0);
    cudaEventRecord(evO0, sG);

    if (c1 > 0) {
        dim3 g1((c1 + 127) / 128, 2);
        gemm_db<false, false><<<g1, 256, SM_G>>>(
            ah + (size_t)c0 * HID, wt + 3 * HID * HID, bo,
            out + (size_t)c0 * HID, nullptr, c1);
    }
    cudaStreamWaitEvent(0, evO0, 0);
}

// round 13
// speedup vs baseline: 1.1892x; 1.0001x over previous
#include <cuda_runtime.h>
#include <cuda_fp16.h>
#include <math.h>
#include <cstdint>

#define HID 256
#define NHEAD 8
#define DK 32
#define MAXN 50048
#define MAXE 1048576

// ---------------- device scratch (allocation-free rule) ----------------
__device__ __half g_qh[MAXN * HID];      // q (fp16)
__device__ __half g_kvh[MAXN * 2 * HID]; // interleaved k|v per node (512 halves)
__device__ __half g_ah[MAXN * HID];      // ctx hi -> later wv hi
__device__ __half g_nh[MAXN * HID];      // node hi
__device__ __half g_wt[4 * HID * HID];   // Wt fp16 [n][k], 4 slots (q,k,v,o)
// CSR
__device__ int g_cnt[MAXN];
__device__ int g_off[MAXN];
__device__ int g_cur[MAXN];
__device__ int g_esrc[MAXE];
__device__ int g_bsum[256];

// ---------------- helpers ----------------
__device__ __forceinline__ uint32_t smem_u32(const void* p) {
    uint32_t a;
    asm("{ .reg .u64 t; cvta.to.shared.u64 t, %1; cvt.u32.u64 %0, t; }"
        : "=r"(a) : "l"(p));
    return a;
}
__device__ __forceinline__ void ldsm4(uint32_t (&r)[4], uint32_t addr) {
    asm volatile("ldmatrix.sync.aligned.m8n8.x4.shared.b16 {%0,%1,%2,%3}, [%4];"
                 : "=r"(r[0]), "=r"(r[1]), "=r"(r[2]), "=r"(r[3]) : "r"(addr));
}
__device__ __forceinline__ void mma16816h(float (&c)[4], const uint32_t (&a)[4],
                                          uint32_t b0, uint32_t b1) {
    asm volatile(
        "mma.sync.aligned.m16n8k16.row.col.f32.f16.f16.f32 "
        "{%0,%1,%2,%3}, {%4,%5,%6,%7}, {%8,%9}, {%0,%1,%2,%3};"
        : "+f"(c[0]), "+f"(c[1]), "+f"(c[2]), "+f"(c[3])
        : "r"(a[0]), "r"(a[1]), "r"(a[2]), "r"(a[3]), "r"(b0), "r"(b1));
}
__device__ __forceinline__ void cpasync16(uint32_t s, const void* g) {
    asm volatile("cp.async.cg.shared.global [%0], [%1], 16;"
                 :: "r"(s), "l"(g) : "memory");
}
__device__ __forceinline__ void cp_commit() {
    asm volatile("cp.async.commit_group;" ::: "memory");
}
template <int N>
__device__ __forceinline__ void cp_wait() {
    asm volatile("cp.async.wait_group %0;" :: "n"(N) : "memory");
}

// ---------------- conversion kernels ----------------
__global__ void conv_w_all(const float* __restrict__ W0, const float* __restrict__ W1,
                           const float* __restrict__ W2, const float* __restrict__ W3) {
    int idx = blockIdx.x * blockDim.x + threadIdx.x;  // 4*65536
    int slot = idx >> 16;
    int r = idx & 65535;
    int k = r >> 8, n = r & 255;
    const float* W = (slot == 0) ? W0 : (slot == 1) ? W1 : (slot == 2) ? W2 : W3;
    g_wt[slot * HID * HID + n * HID + k] = __float2half_rn(W[k * HID + n]);
}

// fp32 -> fp16 hi only
__global__ void conv_hi(const float* __restrict__ in, __half* __restrict__ hi, int n4) {
    int i = blockIdx.x * blockDim.x + threadIdx.x;
    if (i >= n4) return;
    float4 v = ((const float4*)in)[i];
    ((__half2*)hi)[2 * i] = __floats2half2_rn(v.x, v.y);
    ((__half2*)hi)[2 * i + 1] = __floats2half2_rn(v.z, v.w);
}

// ------- HMMA fp16 GEMM, cp.async 3-stage pipeline -----------------------
// C[M,N] = Ah @ Wt^T (+bias). All operands fp16 in global.
// CTA 128x128, 8 warps (4m x 2n), warp tile 32x64, K chunks of 64.
// DUAL: B spans 512 n-rows; output rows are 512 wide (interleaved k|v),
// cols [0,256) -> Cout row offset 0, [256,512) -> offset 256.
#define PADH 72
#define BUFB (128 * PADH * 2)        // 18432 bytes per buffer
#define SM_G (3 * 2 * BUFB)          // 110592 bytes (3 stages x {A,B})

template <bool OUT_HALF, bool DUAL>
__global__ void __launch_bounds__(256, 2) gemm_db(
    const __half* __restrict__ Ah, const __half* __restrict__ Bt,
    const float* __restrict__ bias,
    void* __restrict__ Cout, int M) {
    extern __shared__ char smraw[];
    const uint32_t smb = smem_u32(smraw);

    const int tid = threadIdx.x, wid = tid >> 5, lane = tid & 31;
    const int bm = blockIdx.x * 128, bn = blockIdx.y * 128;
    const int wm = wid & 3, wn = wid >> 2;

    const int CSTR = DUAL ? 2 * HID : HID;  // output row stride

    const uint32_t aRow = lane & 15, aColOff = (lane >> 4) * 8;
    const uint32_t bg = lane >> 3;
    const uint32_t bRowOff = (bg >> 1) * 8 + (lane & 7), bColOff = (bg & 1) * 8;

    float acc[2][8][4];
#pragma unroll
    for (int mb = 0; mb < 2; ++mb)
#pragma unroll
        for (int nb = 0; nb < 8; ++nb)
#pragma unroll
            for (int t = 0; t < 4; ++t) acc[mb][nb][t] = 0.f;

    auto stage = [&](int c, int s) {
        const int k0 = c * 64;
        const uint32_t sb = smb + s * 2 * BUFB;
#pragma unroll
        for (int it = 0; it < 4; ++it) {
            int u = tid + it * 256;  // 1024 = 128 rows * 8 vec8
            int row = u >> 3, col8 = u & 7;
            uint32_t so = (uint32_t)(row * PADH + col8 * 8) * 2;
            int gr = bm + row;
            if (gr < M) {
                cpasync16(sb + so, Ah + (size_t)gr * HID + k0 + col8 * 8);
            }
            cpasync16(sb + BUFB + so,
                      Bt + (size_t)(bn + row) * HID + k0 + col8 * 8);
        }
    };

    stage(0, 0);
    cp_commit();
    stage(1, 1);
    cp_commit();
#pragma unroll
    for (int c = 0; c < 4; ++c) {
        if (c < 3) cp_wait<1>(); else cp_wait<0>();
        __syncthreads();
        if (c + 2 < 4) {
            stage(c + 2, (c + 2) % 3);
            cp_commit();
        }

        const uint32_t st = smb + (c % 3) * 2 * BUFB;
#pragma unroll
        for (int kk = 0; kk < 4; ++kk) {
            const uint32_t kb = kk * 16;
            uint32_t ah[2][4];
#pragma unroll
            for (int mb = 0; mb < 2; ++mb) {
                uint32_t aoff = st + ((wm * 32 + mb * 16 + aRow) * PADH + kb + aColOff) * 2;
                ldsm4(ah[mb], aoff);
            }
#pragma unroll
            for (int half = 0; half < 2; ++half) {
                uint32_t bh[2][4];
#pragma unroll
                for (int p = 0; p < 2; ++p) {
                    uint32_t boff = st + BUFB +
                                    ((wn * 64 + half * 32 + p * 16 + bRowOff) * PADH +
                                     kb + bColOff) * 2;
                    ldsm4(bh[p], boff);
                }
#pragma unroll
                for (int p = 0; p < 2; ++p)
#pragma unroll
                    for (int q = 0; q < 2; ++q) {
                        int nb = half * 4 + p * 2 + q;
#pragma unroll
                        for (int mb = 0; mb < 2; ++mb)
                            mma16816h(acc[mb][nb], ah[mb], bh[p][q * 2], bh[p][q * 2 + 1]);
                    }
            }
        }
    }

    const int rbase = bm + wm * 32 + (lane >> 2);
    const int cbase = bn + wn * 64 + (lane & 3) * 2;  // DUAL: col in [0,512)
#pragma unroll
    for (int mb = 0; mb < 2; ++mb) {
        int r0 = rbase + mb * 16;
#pragma unroll
        for (int nb = 0; nb < 8; ++nb) {
            int col = cbase + nb * 8;
            float bx = 0.f, by = 0.f;
            if (bias) { bx = bias[col]; by = bias[col + 1]; }
            float c0 = acc[mb][nb][0] + bx, c1 = acc[mb][nb][1] + by;
            float c2 = acc[mb][nb][2] + bx, c3 = acc[mb][nb][3] + by;
            if (OUT_HALF) {
                __half* C = (__half*)Cout;
                if (r0 < M) *(__half2*)(C + (size_t)r0 * CSTR + col) = __floats2half2_rn(c0, c1);
                if (r0 + 8 < M) *(__half2*)(C + (size_t)(r0 + 8) * CSTR + col) = __floats2half2_rn(c2, c3);
            } else {
                float* C = (float*)Cout;
                if (r0 < M) *(float2*)(C + (size_t)r0 * CSTR + col) = make_float2(c0, c1);
                if (r0 + 8 < M) *(float2*)(C + (size_t)(r0 + 8) * CSTR + col) = make_float2(c2, c3);
            }
        }
    }
}

// ---------------- CSR build ----------------
__global__ void zero_cnt(int n) {
    int i = blockIdx.x * blockDim.x + threadIdx.x;
    if (i < n) g_cnt[i] = 0;
}
__global__ void hist_kernel(const int* __restrict__ dst, int E) {
    int e = blockIdx.x * blockDim.x + threadIdx.x;
    if (e < E) atomicAdd(&g_cnt[dst[e]], 1);
}
__global__ void scanA(int n) {
    __shared__ int sd[256];
    int i = blockIdx.x * 256 + threadIdx.x;
    sd[threadIdx.x] = (i < n) ? g_cnt[i] : 0;
    __syncthreads();
#pragma unroll
    for (int d = 128; d > 0; d >>= 1) {
        if (threadIdx.x < d) sd[threadIdx.x] += sd[threadIdx.x + d];
        __syncthreads();
    }
    if (threadIdx.x == 0) g_bsum[blockIdx.x] = sd[0];
}
// fused: scan of block sums (local, redundant per block) + local scan
__global__ void scanC(int n, int nb) {
    __shared__ int sb[256];
    __shared__ int sd[256];
    int tid = threadIdx.x;
    // inclusive scan of g_bsum in smem
    int bv = (tid < nb) ? g_bsum[tid] : 0;
    sb[tid] = bv;
    __syncthreads();
#pragma unroll
    for (int d = 1; d < 256; d <<= 1) {
        int t = (tid >= d) ? sb[tid - d] : 0;
        __syncthreads();
        sb[tid] += t;
        __syncthreads();
    }
    int prefix = (blockIdx.x == 0) ? 0 : sb[blockIdx.x - 1];

    int i = blockIdx.x * 256 + tid;
    int v = (i < n) ? g_cnt[i] : 0;
    sd[tid] = v;
    __syncthreads();
#pragma unroll
    for (int d = 1; d < 256; d <<= 1) {
        int t = (tid >= d) ? sd[tid - d] : 0;
        __syncthreads();
        sd[tid] += t;
        __syncthreads();
    }
    if (i < n) {
        int off = prefix + sd[tid] - v;
        g_off[i] = off;
        g_cur[i] = off;
    }
}
__global__ void scatter_kernel(const int* __restrict__ src,
                               const int* __restrict__ dst, int E) {
    int e = blockIdx.x * blockDim.x + threadIdx.x;
    if (e < E) {
        int p = atomicAdd(&g_cur[dst[e]], 1);
        g_esrc[p] = src[e];
    }
}

// ---------------- aggregation: one warp per dst node ----------------
__device__ __forceinline__ float edge_score(const uint4& kk, const float4& q0,
                                            const float4& q1) {
    const __half2* kh = (const __half2*)&kk;
    float2 a = __half22float2(kh[0]), b = __half22float2(kh[1]);
    float2 c = __half22float2(kh[2]), d = __half22float2(kh[3]);
    float p = q0.x * a.x + q0.y * a.y + q0.z * b.x + q0.w * b.y +
              q1.x * c.x + q1.y * c.y + q1.z * d.x + q1.w * d.y;
    p += __shfl_xor_sync(0xffffffffu, p, 1);
    p += __shfl_xor_sync(0xffffffffu, p, 2);
    p *= 0.17677669529663687f;  // 1/sqrt(32)
    p = fminf(5.0f, fmaxf(-5.0f, p));
    return exp2f(p * 1.4426950408889634f);
}
__device__ __forceinline__ void accum_v(float (&acc)[8], float sc, const uint4& vv) {
    const __half2* vh = (const __half2*)&vv;
#pragma unroll
    for (int t = 0; t < 4; ++t) {
        float2 f = __half22float2(vh[t]);
        acc[2 * t] += sc * f.x;
        acc[2 * t + 1] += sc * f.y;
    }
}

__global__ void __launch_bounds__(256) aggregate_kernel(int base, int n) {
    int w = (int)((blockIdx.x * (size_t)blockDim.x + threadIdx.x) >> 5);
    int lane = threadIdx.x & 31;
    if (w >= n) return;
    w += base;
    int beg = g_off[w], deg = g_cnt[w];

    // q row: streaming read (read-once) — keep L2 for k/v
    uint4 qq = __ldcs((const uint4*)(g_qh + (size_t)w * HID + lane * 8));
    const __half2* qh = (const __half2*)&qq;
    float2 qa = __half22float2(qh[0]), qb = __half22float2(qh[1]);
    float2 qc = __half22float2(qh[2]), qd = __half22float2(qh[3]);
    float4 q0 = make_float4(qa.x, qa.y, qb.x, qb.y);
    float4 q1 = make_float4(qc.x, qc.y, qd.x, qd.y);

    float acc[8] = {0, 0, 0, 0, 0, 0, 0, 0};
    float zacc = 0.f;

    const size_t loff = (size_t)lane * 8;

    int j = 0;
    for (; j + 4 <= deg; j += 4) {
        int s0 = __ldcs(g_esrc + beg + j + 0);
        int s1 = __ldcs(g_esrc + beg + j + 1);
        int s2 = __ldcs(g_esrc + beg + j + 2);
        int s3 = __ldcs(g_esrc + beg + j + 3);
        const __half* b0 = g_kvh + (size_t)s0 * (2 * HID);
        const __half* b1 = g_kvh + (size_t)s1 * (2 * HID);
        const __half* b2 = g_kvh + (size_t)s2 * (2 * HID);
        const __half* b3 = g_kvh + (size_t)s3 * (2 * HID);
        uint4 k0 = *(const uint4*)(b0 + loff);
        uint4 k1 = *(const uint4*)(b1 + loff);
        uint4 k2 = *(const uint4*)(b2 + loff);
        uint4 k3 = *(const uint4*)(b3 + loff);
        uint4 v0 = *(const uint4*)(b0 + HID + loff);
        uint4 v1 = *(const uint4*)(b1 + HID + loff);
        uint4 v2 = *(const uint4*)(b2 + HID + loff);
        uint4 v3 = *(const uint4*)(b3 + HID + loff);
        float sc0 = edge_score(k0, q0, q1);
        float sc1 = edge_score(k1, q0, q1);
        float sc2 = edge_score(k2, q0, q1);
        float sc3 = edge_score(k3, q0, q1);
        accum_v(acc, sc0, v0);
        accum_v(acc, sc1, v1);
        accum_v(acc, sc2, v2);
        accum_v(acc, sc3, v3);
        zacc += (sc0 + sc1) + (sc2 + sc3);
    }
    for (; j < deg; ++j) {
        int s0 = __ldcs(g_esrc + beg + j);
        const __half* b0 = g_kvh + (size_t)s0 * (2 * HID);
        uint4 k0 = *(const uint4*)(b0 + loff);
        uint4 v0 = *(const uint4*)(b0 + HID + loff);
        float sc0 = edge_score(k0, q0, q1);
        accum_v(acc, sc0, v0);
        zacc += sc0;
    }

    // write normalized wv as fp16 hi (streaming store — write-once)
    float inv = 1.0f / zacc;
    uint4 UH;
    uint32_t* uh = (uint32_t*)&UH;
#pragma unroll
    for (int t = 0; t < 4; ++t) {
        __half2 h = __floats2half2_rn(acc[2 * t] * inv, acc[2 * t + 1] * inv);
        uh[t] = *(uint32_t*)&h;
    }
    __stcs((uint4*)(g_ah + (size_t)w * HID + loff), UH);
}

// ---------------- launch ----------------
extern "C" void kernel_launch(void* const* d_in, const int* in_sizes, int n_in,
                              void* d_out, int out_size) {
    const float* context = (const float*)d_in[0];
    const float* node    = (const float*)d_in[1];
    const float* Wq      = (const float*)d_in[2];
    const float* bq      = (const float*)d_in[3];
    const float* Wk      = (const float*)d_in[4];
    const float* Wv      = (const float*)d_in[5];
    const float* Wo      = (const float*)d_in[6];
    const float* bo      = (const float*)d_in[7];
    const int*   src     = (const int*)d_in[8];
    const int*   dst     = (const int*)d_in[9];
    float* out = (float*)d_out;

    int Nq = in_sizes[0] / HID;
    int Ns = in_sizes[1] / HID;
    int E  = in_sizes[8];

    __half *qb, *kvb, *ah, *nh, *wt;
    cudaGetSymbolAddress((void**)&qb, g_qh);
    cudaGetSymbolAddress((void**)&kvb, g_kvh);
    cudaGetSymbolAddress((void**)&ah, g_ah);
    cudaGetSymbolAddress((void**)&nh, g_nh);
    cudaGetSymbolAddress((void**)&wt, g_wt);

    static bool inited = false;
    static cudaStream_t sG, sC;
    static cudaEvent_t evF, evW, evG, evC, evA0, evO0;
    if (!inited) {
        cudaFuncSetAttribute((const void*)gemm_db<true, false>,
                             cudaFuncAttributeMaxDynamicSharedMemorySize, SM_G);
        cudaFuncSetAttribute((const void*)gemm_db<true, true>,
                             cudaFuncAttributeMaxDynamicSharedMemorySize, SM_G);
        cudaFuncSetAttribute((const void*)gemm_db<false, false>,
                             cudaFuncAttributeMaxDynamicSharedMemorySize, SM_G);
        cudaStreamCreateWithFlags(&sG, cudaStreamNonBlocking);
        cudaStreamCreateWithFlags(&sC, cudaStreamNonBlocking);
        cudaEventCreateWithFlags(&evF, cudaEventDisableTiming);
        cudaEventCreateWithFlags(&evW, cudaEventDisableTiming);
        cudaEventCreateWithFlags(&evG, cudaEventDisableTiming);
        cudaEventCreateWithFlags(&evC, cudaEventDisableTiming);
        cudaEventCreateWithFlags(&evA0, cudaEventDisableTiming);
        cudaEventCreateWithFlags(&evO0, cudaEventDisableTiming);
        inited = true;
    }

    dim3 gq((Ns + 127) / 128, 2);
    dim3 gkv((Nq + 127) / 128, 4);  // fused k+v: N=512 interleaved output
    int nb = (Ns + 255) / 256;
    int n4s = Ns * HID / 4, n4q = Nq * HID / 4;

    // fork
    cudaEventRecord(evF, 0);
    cudaStreamWaitEvent(sG, evF, 0);
    cudaStreamWaitEvent(sC, evF, 0);

    // ---- stream sG: weights + ctx conv + fused kv GEMM ----
    conv_w_all<<<1024, 256, 0, sG>>>(Wq, Wk, Wv, Wo);
    cudaEventRecord(evW, sG);
    conv_hi<<<(n4q + 255) / 256, 256, 0, sG>>>(context, ah, n4q);
    gemm_db<true, true><<<gkv, 256, SM_G, sG>>>(
        ah, wt + 1 * HID * HID, nullptr, kvb, Nq);
    cudaEventRecord(evG, sG);

    // ---- stream sC: CSR + node conv + q GEMM ----
    zero_cnt<<<nb, 256, 0, sC>>>(Ns);
    hist_kernel<<<(E + 255) / 256, 256, 0, sC>>>(dst, E);
    scanA<<<nb, 256, 0, sC>>>(Ns);
    scanC<<<nb, 256, 0, sC>>>(Ns, nb);
    scatter_kernel<<<(E + 255) / 256, 256, 0, sC>>>(src, dst, E);
    conv_hi<<<(n4s + 255) / 256, 256, 0, sC>>>(node, nh, n4s);
    cudaStreamWaitEvent(sC, evW, 0);
    gemm_db<true, false><<<gq, 256, SM_G, sC>>>(
        nh, wt + 0 * HID * HID, bq, qb, Ns);
    cudaEventRecord(evC, sC);

    // ---- join onto default stream ----
    cudaStreamWaitEvent(0, evG, 0);
    cudaStreamWaitEvent(0, evC, 0);

    // ---- aggregation + output projection, asymmetric ~70/30 pipeline ----
    int nblk = (Ns + 127) / 128;
    int c0 = ((nblk * 7 + 9) / 10) * 128;  // ~70% rounded to tile
    if (c0 > Ns) c0 = Ns;
    int c1 = Ns - c0;

    aggregate_kernel<<<(c0 + 7) / 8, 256>>>(0, c0);
    cudaEventRecord(evA0, 0);
    if (c1 > 0) aggregate_kernel<<<(c1 + 7) / 8, 256>>>(c0, c1);

    cudaStreamWaitEvent(sG, evA0, 0);
    dim3 g0((c0 + 127) / 128, 2);
    gemm_db<false, false><<<g0, 256, SM_G, sG>>>(
        ah, wt + 3 * HID * HID, bo, out, c0);
    cudaEventRecord(evO0, sG);

    if (c1 > 0) {
        dim3 g1((c1 + 127) / 128, 2);
        gemm_db<false, false><<<g1, 256, SM_G>>>(
            ah + (size_t)c0 * HID, wt + 3 * HID * HID, bo,
            out + (size_t)c0 * HID, c1);
    }
    cudaStreamWaitEvent(0, evO0, 0);
}

// round 14
// speedup vs baseline: 1.2074x; 1.0153x over previous
#include <cuda_runtime.h>
#include <cuda_fp16.h>
#include <math.h>
#include <cstdint>

#define HID 256
#define NHEAD 8
#define DK 32
#define MAXN 50048
#define MAXE 1048576

// ---------------- device scratch (allocation-free rule) ----------------
__device__ __half g_qh[MAXN * HID];      // q (fp16)
__device__ __half g_kvh[MAXN * 2 * HID]; // interleaved k|v per node (512 halves)
__device__ __half g_ah[MAXN * HID];      // ctx hi -> later wv hi
__device__ __half g_nh[MAXN * HID];      // node hi
__device__ __half g_wt[4 * HID * HID];   // Wt fp16 [n][k], 4 slots (q,k,v,o)
// CSR
__device__ int g_cnt[MAXN];
__device__ int g_off[MAXN];
__device__ int g_cur[MAXN];
__device__ int g_esrc[MAXE];
__device__ int g_bsum[256];

// ---------------- helpers ----------------
__device__ __forceinline__ uint32_t smem_u32(const void* p) {
    uint32_t a;
    asm("{ .reg .u64 t; cvta.to.shared.u64 t, %1; cvt.u32.u64 %0, t; }"
        : "=r"(a) : "l"(p));
    return a;
}
__device__ __forceinline__ void ldsm4(uint32_t (&r)[4], uint32_t addr) {
    asm volatile("ldmatrix.sync.aligned.m8n8.x4.shared.b16 {%0,%1,%2,%3}, [%4];"
                 : "=r"(r[0]), "=r"(r[1]), "=r"(r[2]), "=r"(r[3]) : "r"(addr));
}
__device__ __forceinline__ void mma16816h(float (&c)[4], const uint32_t (&a)[4],
                                          uint32_t b0, uint32_t b1) {
    asm volatile(
        "mma.sync.aligned.m16n8k16.row.col.f32.f16.f16.f32 "
        "{%0,%1,%2,%3}, {%4,%5,%6,%7}, {%8,%9}, {%0,%1,%2,%3};"
        : "+f"(c[0]), "+f"(c[1]), "+f"(c[2]), "+f"(c[3])
        : "r"(a[0]), "r"(a[1]), "r"(a[2]), "r"(a[3]), "r"(b0), "r"(b1));
}
__device__ __forceinline__ void cpasync16(uint32_t s, const void* g) {
    asm volatile("cp.async.cg.shared.global [%0], [%1], 16;"
                 :: "r"(s), "l"(g) : "memory");
}
__device__ __forceinline__ void cp_commit() {
    asm volatile("cp.async.commit_group;" ::: "memory");
}
template <int N>
__device__ __forceinline__ void cp_wait() {
    asm volatile("cp.async.wait_group %0;" :: "n"(N) : "memory");
}

// ---------------- conversion kernels ----------------
__global__ void conv_w_all(const float* __restrict__ W0, const float* __restrict__ W1,
                           const float* __restrict__ W2, const float* __restrict__ W3) {
    int idx = blockIdx.x * blockDim.x + threadIdx.x;  // 4*65536
    int slot = idx >> 16;
    int r = idx & 65535;
    int k = r >> 8, n = r & 255;
    const float* W = (slot == 0) ? W0 : (slot == 1) ? W1 : (slot == 2) ? W2 : W3;
    g_wt[slot * HID * HID + n * HID + k] = __float2half_rn(W[k * HID + n]);
}

// fp32 -> fp16 hi only
__global__ void conv_hi(const float* __restrict__ in, __half* __restrict__ hi, int n4) {
    int i = blockIdx.x * blockDim.x + threadIdx.x;
    if (i >= n4) return;
    float4 v = ((const float4*)in)[i];
    ((__half2*)hi)[2 * i] = __floats2half2_rn(v.x, v.y);
    ((__half2*)hi)[2 * i + 1] = __floats2half2_rn(v.z, v.w);
}

// ------- HMMA fp16 GEMM, cp.async 3-stage pipeline -----------------------
// C[M,N] = Ah @ Wt^T (+bias). All operands fp16 in global.
// CTA 128x128, 8 warps (4m x 2n), warp tile 32x64, K chunks of 64.
// DUAL: B spans 512 n-rows; output rows are 512 wide (interleaved k|v).
#define PADH 72
#define BUFB (128 * PADH * 2)        // 18432 bytes per buffer
#define SM_G (3 * 2 * BUFB)          // 110592 bytes (3 stages x {A,B})

template <bool OUT_HALF, bool DUAL>
__global__ void __launch_bounds__(256, 2) gemm_db(
    const __half* __restrict__ Ah, const __half* __restrict__ Bt,
    const float* __restrict__ bias,
    void* __restrict__ Cout, int M) {
    extern __shared__ char smraw[];
    const uint32_t smb = smem_u32(smraw);

    const int tid = threadIdx.x, wid = tid >> 5, lane = tid & 31;
    const int bm = blockIdx.x * 128, bn = blockIdx.y * 128;
    const int wm = wid & 3, wn = wid >> 2;

    const int CSTR = DUAL ? 2 * HID : HID;  // output row stride

    const uint32_t aRow = lane & 15, aColOff = (lane >> 4) * 8;
    const uint32_t bg = lane >> 3;
    const uint32_t bRowOff = (bg >> 1) * 8 + (lane & 7), bColOff = (bg & 1) * 8;

    float acc[2][8][4];
#pragma unroll
    for (int mb = 0; mb < 2; ++mb)
#pragma unroll
        for (int nb = 0; nb < 8; ++nb)
#pragma unroll
            for (int t = 0; t < 4; ++t) acc[mb][nb][t] = 0.f;

    auto stage = [&](int c, int s) {
        const int k0 = c * 64;
        const uint32_t sb = smb + s * 2 * BUFB;
#pragma unroll
        for (int it = 0; it < 4; ++it) {
            int u = tid + it * 256;  // 1024 = 128 rows * 8 vec8
            int row = u >> 3, col8 = u & 7;
            uint32_t so = (uint32_t)(row * PADH + col8 * 8) * 2;
            int gr = bm + row;
            if (gr < M) {
                cpasync16(sb + so, Ah + (size_t)gr * HID + k0 + col8 * 8);
            }
            cpasync16(sb + BUFB + so,
                      Bt + (size_t)(bn + row) * HID + k0 + col8 * 8);
        }
    };

    stage(0, 0);
    cp_commit();
    stage(1, 1);
    cp_commit();
#pragma unroll
    for (int c = 0; c < 4; ++c) {
        if (c < 3) cp_wait<1>(); else cp_wait<0>();
        __syncthreads();
        if (c + 2 < 4) {
            stage(c + 2, (c + 2) % 3);
            cp_commit();
        }

        const uint32_t st = smb + (c % 3) * 2 * BUFB;
#pragma unroll
        for (int kk = 0; kk < 4; ++kk) {
            const uint32_t kb = kk * 16;
            uint32_t ah[2][4];
#pragma unroll
            for (int mb = 0; mb < 2; ++mb) {
                uint32_t aoff = st + ((wm * 32 + mb * 16 + aRow) * PADH + kb + aColOff) * 2;
                ldsm4(ah[mb], aoff);
            }
#pragma unroll
            for (int half = 0; half < 2; ++half) {
                uint32_t bh[2][4];
#pragma unroll
                for (int p = 0; p < 2; ++p) {
                    uint32_t boff = st + BUFB +
                                    ((wn * 64 + half * 32 + p * 16 + bRowOff) * PADH +
                                     kb + bColOff) * 2;
                    ldsm4(bh[p], boff);
                }
#pragma unroll
                for (int p = 0; p < 2; ++p)
#pragma unroll
                    for (int q = 0; q < 2; ++q) {
                        int nb = half * 4 + p * 2 + q;
#pragma unroll
                        for (int mb = 0; mb < 2; ++mb)
                            mma16816h(acc[mb][nb], ah[mb], bh[p][q * 2], bh[p][q * 2 + 1]);
                    }
            }
        }
    }

    const int rbase = bm + wm * 32 + (lane >> 2);
    const int cbase = bn + wn * 64 + (lane & 3) * 2;  // DUAL: col in [0,512)
#pragma unroll
    for (int mb = 0; mb < 2; ++mb) {
        int r0 = rbase + mb * 16;
#pragma unroll
        for (int nb = 0; nb < 8; ++nb) {
            int col = cbase + nb * 8;
            float bx = 0.f, by = 0.f;
            if (bias) { bx = bias[col]; by = bias[col + 1]; }
            float c0 = acc[mb][nb][0] + bx, c1 = acc[mb][nb][1] + by;
            float c2 = acc[mb][nb][2] + bx, c3 = acc[mb][nb][3] + by;
            if (OUT_HALF) {
                __half* C = (__half*)Cout;
                if (r0 < M) *(__half2*)(C + (size_t)r0 * CSTR + col) = __floats2half2_rn(c0, c1);
                if (r0 + 8 < M) *(__half2*)(C + (size_t)(r0 + 8) * CSTR + col) = __floats2half2_rn(c2, c3);
            } else {
                float* C = (float*)Cout;
                if (r0 < M) *(float2*)(C + (size_t)r0 * CSTR + col) = make_float2(c0, c1);
                if (r0 + 8 < M) *(float2*)(C + (size_t)(r0 + 8) * CSTR + col) = make_float2(c2, c3);
            }
        }
    }
}

// ---------------- CSR build ----------------
__global__ void zero_cnt(int n) {
    int i = blockIdx.x * blockDim.x + threadIdx.x;
    if (i < n) g_cnt[i] = 0;
}
__global__ void hist_kernel(const int* __restrict__ dst, int E) {
    int e = blockIdx.x * blockDim.x + threadIdx.x;
    if (e < E) atomicAdd(&g_cnt[dst[e]], 1);
}
__global__ void scanA(int n) {
    __shared__ int sd[256];
    int i = blockIdx.x * 256 + threadIdx.x;
    sd[threadIdx.x] = (i < n) ? g_cnt[i] : 0;
    __syncthreads();
#pragma unroll
    for (int d = 128; d > 0; d >>= 1) {
        if (threadIdx.x < d) sd[threadIdx.x] += sd[threadIdx.x + d];
        __syncthreads();
    }
    if (threadIdx.x == 0) g_bsum[blockIdx.x] = sd[0];
}
// fused: scan of block sums (local, redundant per block) + local scan
__global__ void scanC(int n, int nb) {
    __shared__ int sb[256];
    __shared__ int sd[256];
    int tid = threadIdx.x;
    int bv = (tid < nb) ? g_bsum[tid] : 0;
    sb[tid] = bv;
    __syncthreads();
#pragma unroll
    for (int d = 1; d < 256; d <<= 1) {
        int t = (tid >= d) ? sb[tid - d] : 0;
        __syncthreads();
        sb[tid] += t;
        __syncthreads();
    }
    int prefix = (blockIdx.x == 0) ? 0 : sb[blockIdx.x - 1];

    int i = blockIdx.x * 256 + tid;
    int v = (i < n) ? g_cnt[i] : 0;
    sd[tid] = v;
    __syncthreads();
#pragma unroll
    for (int d = 1; d < 256; d <<= 1) {
        int t = (tid >= d) ? sd[tid - d] : 0;
        __syncthreads();
        sd[tid] += t;
        __syncthreads();
    }
    if (i < n) {
        int off = prefix + sd[tid] - v;
        g_off[i] = off;
        g_cur[i] = off;
    }
}
__global__ void scatter_kernel(const int* __restrict__ src,
                               const int* __restrict__ dst, int E) {
    int e = blockIdx.x * blockDim.x + threadIdx.x;
    if (e < E) {
        int p = atomicAdd(&g_cur[dst[e]], 1);
        g_esrc[p] = src[e];
    }
}

// ---------------- aggregation: one warp per dst node ----------------
__device__ __forceinline__ float edge_score(const uint4& kk, const float4& q0,
                                            const float4& q1) {
    const __half2* kh = (const __half2*)&kk;
    float2 a = __half22float2(kh[0]), b = __half22float2(kh[1]);
    float2 c = __half22float2(kh[2]), d = __half22float2(kh[3]);
    float p = q0.x * a.x + q0.y * a.y + q0.z * b.x + q0.w * b.y +
              q1.x * c.x + q1.y * c.y + q1.z * d.x + q1.w * d.y;
    p += __shfl_xor_sync(0xffffffffu, p, 1);
    p += __shfl_xor_sync(0xffffffffu, p, 2);
    p *= 0.17677669529663687f;  // 1/sqrt(32)
    p = fminf(5.0f, fmaxf(-5.0f, p));
    return exp2f(p * 1.4426950408889634f);
}
__device__ __forceinline__ void accum_v(float (&acc)[8], float sc, const uint4& vv) {
    const __half2* vh = (const __half2*)&vv;
#pragma unroll
    for (int t = 0; t < 4; ++t) {
        float2 f = __half22float2(vh[t]);
        acc[2 * t] += sc * f.x;
        acc[2 * t + 1] += sc * f.y;
    }
}

__global__ void __launch_bounds__(256) aggregate_kernel(int base, int n) {
    int w = (int)((blockIdx.x * (size_t)blockDim.x + threadIdx.x) >> 5);
    int lane = threadIdx.x & 31;
    if (w >= n) return;
    w += base;
    int beg = g_off[w], deg = g_cnt[w];

    uint4 qq = __ldcs((const uint4*)(g_qh + (size_t)w * HID + lane * 8));
    const __half2* qh = (const __half2*)&qq;
    float2 qa = __half22float2(qh[0]), qb = __half22float2(qh[1]);
    float2 qc = __half22float2(qh[2]), qd = __half22float2(qh[3]);
    float4 q0 = make_float4(qa.x, qa.y, qb.x, qb.y);
    float4 q1 = make_float4(qc.x, qc.y, qd.x, qd.y);

    float acc[8] = {0, 0, 0, 0, 0, 0, 0, 0};
    float zacc = 0.f;

    const size_t loff = (size_t)lane * 8;

    int j = 0;
    for (; j + 4 <= deg; j += 4) {
        int s0 = __ldcs(g_esrc + beg + j + 0);
        int s1 = __ldcs(g_esrc + beg + j + 1);
        int s2 = __ldcs(g_esrc + beg + j + 2);
        int s3 = __ldcs(g_esrc + beg + j + 3);
        const __half* b0 = g_kvh + (size_t)s0 * (2 * HID);
        const __half* b1 = g_kvh + (size_t)s1 * (2 * HID);
        const __half* b2 = g_kvh + (size_t)s2 * (2 * HID);
        const __half* b3 = g_kvh + (size_t)s3 * (2 * HID);
        uint4 k0 = *(const uint4*)(b0 + loff);
        uint4 k1 = *(const uint4*)(b1 + loff);
        uint4 k2 = *(const uint4*)(b2 + loff);
        uint4 k3 = *(const uint4*)(b3 + loff);
        uint4 v0 = *(const uint4*)(b0 + HID + loff);
        uint4 v1 = *(const uint4*)(b1 + HID + loff);
        uint4 v2 = *(const uint4*)(b2 + HID + loff);
        uint4 v3 = *(const uint4*)(b3 + HID + loff);
        float sc0 = edge_score(k0, q0, q1);
        float sc1 = edge_score(k1, q0, q1);
        float sc2 = edge_score(k2, q0, q1);
        float sc3 = edge_score(k3, q0, q1);
        accum_v(acc, sc0, v0);
        accum_v(acc, sc1, v1);
        accum_v(acc, sc2, v2);
        accum_v(acc, sc3, v3);
        zacc += (sc0 + sc1) + (sc2 + sc3);
    }
    for (; j < deg; ++j) {
        int s0 = __ldcs(g_esrc + beg + j);
        const __half* b0 = g_kvh + (size_t)s0 * (2 * HID);
        uint4 k0 = *(const uint4*)(b0 + loff);
        uint4 v0 = *(const uint4*)(b0 + HID + loff);
        float sc0 = edge_score(k0, q0, q1);
        accum_v(acc, sc0, v0);
        zacc += sc0;
    }

    float inv = 1.0f / zacc;
    uint4 UH;
    uint32_t* uh = (uint32_t*)&UH;
#pragma unroll
    for (int t = 0; t < 4; ++t) {
        __half2 h = __floats2half2_rn(acc[2 * t] * inv, acc[2 * t + 1] * inv);
        uh[t] = *(uint32_t*)&h;
    }
    __stcs((uint4*)(g_ah + (size_t)w * HID + loff), UH);
}

// ---------------- launch ----------------
extern "C" void kernel_launch(void* const* d_in, const int* in_sizes, int n_in,
                              void* d_out, int out_size) {
    const float* context = (const float*)d_in[0];
    const float* node    = (const float*)d_in[1];
    const float* Wq      = (const float*)d_in[2];
    const float* bq      = (const float*)d_in[3];
    const float* Wk      = (const float*)d_in[4];
    const float* Wv      = (const float*)d_in[5];
    const float* Wo      = (const float*)d_in[6];
    const float* bo      = (const float*)d_in[7];
    const int*   src     = (const int*)d_in[8];
    const int*   dst     = (const int*)d_in[9];
    float* out = (float*)d_out;

    int Nq = in_sizes[0] / HID;
    int Ns = in_sizes[1] / HID;
    int E  = in_sizes[8];

    __half *qb, *kvb, *ah, *nh, *wt;
    cudaGetSymbolAddress((void**)&qb, g_qh);
    cudaGetSymbolAddress((void**)&kvb, g_kvh);
    cudaGetSymbolAddress((void**)&ah, g_ah);
    cudaGetSymbolAddress((void**)&nh, g_nh);
    cudaGetSymbolAddress((void**)&wt, g_wt);

    static bool inited = false;
    static cudaStream_t sG, sC, sD;
    static cudaEvent_t evF, evW, evD, evSc, evS, evG, evC, evA0, evO0;
    if (!inited) {
        cudaFuncSetAttribute((const void*)gemm_db<true, false>,
                             cudaFuncAttributeMaxDynamicSharedMemorySize, SM_G);
        cudaFuncSetAttribute((const void*)gemm_db<true, true>,
                             cudaFuncAttributeMaxDynamicSharedMemorySize, SM_G);
        cudaFuncSetAttribute((const void*)gemm_db<false, false>,
                             cudaFuncAttributeMaxDynamicSharedMemorySize, SM_G);
        cudaStreamCreateWithFlags(&sG, cudaStreamNonBlocking);
        cudaStreamCreateWithFlags(&sC, cudaStreamNonBlocking);
        cudaStreamCreateWithFlags(&sD, cudaStreamNonBlocking);
        cudaEventCreateWithFlags(&evF, cudaEventDisableTiming);
        cudaEventCreateWithFlags(&evW, cudaEventDisableTiming);
        cudaEventCreateWithFlags(&evD, cudaEventDisableTiming);
        cudaEventCreateWithFlags(&evSc, cudaEventDisableTiming);
        cudaEventCreateWithFlags(&evS, cudaEventDisableTiming);
        cudaEventCreateWithFlags(&evG, cudaEventDisableTiming);
        cudaEventCreateWithFlags(&evC, cudaEventDisableTiming);
        cudaEventCreateWithFlags(&evA0, cudaEventDisableTiming);
        cudaEventCreateWithFlags(&evO0, cudaEventDisableTiming);
        inited = true;
    }

    dim3 gq((Ns + 127) / 128, 2);
    dim3 gkv((Nq + 127) / 128, 4);  // fused k+v: N=512 interleaved output
    int nb = (Ns + 255) / 256;
    int n4s = Ns * HID / 4, n4q = Nq * HID / 4;

    // fork
    cudaEventRecord(evF, 0);
    cudaStreamWaitEvent(sG, evF, 0);
    cudaStreamWaitEvent(sC, evF, 0);
    cudaStreamWaitEvent(sD, evF, 0);

    // ---- stream sD: ctx conversion (parallel with conv_w) ----
    conv_hi<<<(n4q + 255) / 256, 256, 0, sD>>>(context, ah, n4q);
    cudaEventRecord(evD, sD);

    // ---- stream sG: weights, then fused kv GEMM (waits ctx conv) ----
    conv_w_all<<<1024, 256, 0, sG>>>(Wq, Wk, Wv, Wo);
    cudaEventRecord(evW, sG);
    cudaStreamWaitEvent(sG, evD, 0);
    gemm_db<true, true><<<gkv, 256, SM_G, sG>>>(
        ah, wt + 1 * HID * HID, nullptr, kvb, Nq);
    cudaEventRecord(evG, sG);

    // ---- stream sC: node conv + CSR front + q GEMM ----
    conv_hi<<<(n4s + 255) / 256, 256, 0, sC>>>(node, nh, n4s);
    zero_cnt<<<nb, 256, 0, sC>>>(Ns);
    hist_kernel<<<(E + 255) / 256, 256, 0, sC>>>(dst, E);
    scanA<<<nb, 256, 0, sC>>>(Ns);
    scanC<<<nb, 256, 0, sC>>>(Ns, nb);
    cudaEventRecord(evSc, sC);
    cudaStreamWaitEvent(sC, evW, 0);
    gemm_db<true, false><<<gq, 256, SM_G, sC>>>(
        nh, wt + 0 * HID * HID, bq, qb, Ns);
    cudaEventRecord(evC, sC);

    // ---- stream sD: scatter (after scanC), overlaps q/kv GEMMs ----
    cudaStreamWaitEvent(sD, evSc, 0);
    scatter_kernel<<<(E + 255) / 256, 256, 0, sD>>>(src, dst, E);
    cudaEventRecord(evS, sD);

    // ---- join onto default stream ----
    cudaStreamWaitEvent(0, evG, 0);
    cudaStreamWaitEvent(0, evC, 0);
    cudaStreamWaitEvent(0, evS, 0);

    // ---- aggregation + output projection, asymmetric ~70/30 pipeline ----
    int nblk = (Ns + 127) / 128;
    int c0 = ((nblk * 7 + 9) / 10) * 128;  // ~70% rounded to tile
    if (c0 > Ns) c0 = Ns;
    int c1 = Ns - c0;

    aggregate_kernel<<<(c0 + 7) / 8, 256>>>(0, c0);
    cudaEventRecord(evA0, 0);
    if (c1 > 0) aggregate_kernel<<<(c1 + 7) / 8, 256>>>(c0, c1);

    cudaStreamWaitEvent(sG, evA0, 0);
    dim3 g0((c0 + 127) / 128, 2);
    gemm_db<false, false><<<g0, 256, SM_G, sG>>>(
        ah, wt + 3 * HID * HID, bo, out, c0);
    cudaEventRecord(evO0, sG);

    if (c1 > 0) {
        dim3 g1((c1 + 127) / 128, 2);
        gemm_db<false, false><<<g1, 256, SM_G>>>(
            ah + (size_t)c0 * HID, wt + 3 * HID * HID, bo,
            out + (size_t)c0 * HID, c1);
    }
    cudaStreamWaitEvent(0, evO0, 0);
}